// round 11
// baseline (speedup 1.0000x reference)
#include <cuda_runtime.h>
#include <cuda_bf16.h>
#include <stdint.h>

#define NMB  4
#define CNUM 17
#define HNUM 8
#define BNUM 8
#define SLEN 512
#define DDIM 64
#define TI   64
#define JT   128
#define MAXCH 12
#define AST  136   // A' row stride (bf16): 272B -> conflict-free ldmatrix
#define BST  136   // B' row stride (bf16)

// Premixed W1_: [C][h][m][n]  (n-major: lane-coalesced reads)
__device__ float g_W[CNUM * HNUM * DDIM * DDIM];

// ---- packed f32x2 helpers (phase A) ----
union F4U   { float4 f4; unsigned long long u[2]; };
union U64F2 { unsigned long long u; float2 f; };
__device__ __forceinline__ void ffma2(unsigned long long& d,
                                      unsigned long long a,
                                      unsigned long long b) {
    asm("fma.rn.f32x2 %0, %1, %2, %0;" : "+l"(d) : "l"(a), "l"(b));
}
__device__ __forceinline__ unsigned long long pack2(float x, float y) {
    unsigned long long r;
    asm("mov.b64 %0, {%1, %2};" : "=l"(r) : "f"(x), "f"(y));
    return r;
}
__device__ __forceinline__ float hadd2(unsigned long long a) {
    U64F2 x; x.u = a; return x.f.x + x.f.y;
}

// ---- HMMA helpers (base-arch: ldmatrix + mma.sync bf16) ----
#define LDSM4(r, a) \
    asm volatile("ldmatrix.sync.aligned.m8n8.x4.shared.b16 {%0,%1,%2,%3}, [%4];" \
        : "=r"((r)[0]), "=r"((r)[1]), "=r"((r)[2]), "=r"((r)[3]) : "r"(a))

#define MMA16816(d, a, b0v, b1v) \
    asm volatile("mma.sync.aligned.m16n8k16.row.col.f32.bf16.bf16.f32 " \
        "{%0,%1,%2,%3}, {%4,%5,%6,%7}, {%8,%9}, {%0,%1,%2,%3};" \
        : "+f"((d)[0]), "+f"((d)[1]), "+f"((d)[2]), "+f"((d)[3]) \
        : "r"((a)[0]), "r"((a)[1]), "r"((a)[2]), "r"((a)[3]), "r"(b0v), "r"(b1v))

// ---------------- Kernel 1: premix W ----------------
__global__ void wmix_kernel(const float* __restrict__ W1,
                            const float* __restrict__ alpha1) {
    int c = blockIdx.x, h = blockIdx.y;
    float a[NMB];
#pragma unroll
    for (int B = 0; B < NMB; B++) a[B] = alpha1[(c * NMB + B) * HNUM + h];
    float mx = fmaxf(fmaxf(a[0], a[1]), fmaxf(a[2], a[3]));
    float w[NMB], s = 0.f;
#pragma unroll
    for (int B = 0; B < NMB; B++) { w[B] = __expf(a[B] - mx); s += w[B]; }
    float inv = 1.f / s;
#pragma unroll
    for (int B = 0; B < NMB; B++) w[B] *= inv;
    float* dst = g_W + (c * HNUM + h) * DDIM * DDIM;
    const float* src = W1 + h * DDIM * DDIM;
    for (int e = threadIdx.x; e < DDIM * DDIM; e += blockDim.x) {
        float v = 0.f;
#pragma unroll
        for (int B = 0; B < NMB; B++) v += w[B] * src[B * HNUM * DDIM * DDIM + e];
        dst[e] = v;
    }
}

// ---------------- shared layout (bytes) ----------------
#define OFF_Q    0                     // 64*64*4   = 16384
#define OFF_A    16384                 // 64*AST*2  = 17408
#define OFF_B    (16384 + 17408)       // 128*BST*2 = 34816
#define OFF_INT  (OFF_B + 34816)
// ints: bj_all[512] jperm[512] rlist[256] jcnt8 joff8 jpos8 rcnt8 cls12 coff12 clen12 nch4
#define NINTS (512 + 512 + 256 + 8 + 8 + 8 + 8 + MAXCH * 3 + 4)
#define SMEM_BYTES (OFF_INT + NINTS * 4)

// phase-A row pair: U fp32 -> bf16 hi/lo into A' slices [UH | UL].
// W cached 16 u64 regs at a time (two m-halves) to keep register count low.
__device__ __forceinline__ void urow2(const float* Qs, unsigned char* Ab,
                                      const float* Wcol, int ia, int ib, int n) {
    const F4U* qa = (const F4U*)(Qs + ia * DDIM);
    const F4U* qb = (const F4U*)(Qs + ib * DDIM);
    unsigned long long a0 = 0, b0 = 0;
#pragma unroll
    for (int half = 0; half < 2; half++) {
        unsigned long long wp[16];
        const float* Wh = Wcol + half * 32 * DDIM;
#pragma unroll
        for (int m2 = 0; m2 < 16; m2++)
            wp[m2] = pack2(Wh[(2 * m2) * DDIM], Wh[(2 * m2 + 1) * DDIM]);
#pragma unroll
        for (int mb = 0; mb < 8; mb++) {
            F4U va = qa[half * 8 + mb], vb = qb[half * 8 + mb];
            ffma2(a0, va.u[0], wp[2 * mb]);
            ffma2(a0, va.u[1], wp[2 * mb + 1]);
            ffma2(b0, vb.u[0], wp[2 * mb]);
            ffma2(b0, vb.u[1], wp[2 * mb + 1]);
        }
    }
    float ua = hadd2(a0), ub = hadd2(b0);
    __nv_bfloat16 hia = __float2bfloat16(ua);
    __nv_bfloat16 loa = __float2bfloat16(ua - __bfloat162float(hia));
    __nv_bfloat16 hib = __float2bfloat16(ub);
    __nv_bfloat16 lob = __float2bfloat16(ub - __bfloat162float(hib));
    uint32_t oa = (uint32_t)(ia * AST + n) * 2;
    uint32_t ob = (uint32_t)(ib * AST + n) * 2;
    *(__nv_bfloat16*)(Ab + oa)       = hia;
    *(__nv_bfloat16*)(Ab + oa + 128) = loa;
    *(__nv_bfloat16*)(Ab + ob)       = hib;
    *(__nv_bfloat16*)(Ab + ob + 128) = lob;
}

__device__ __forceinline__ void cvt4(float4 v, uint32_t& hw0, uint32_t& hw1,
                                     uint32_t& lw0, uint32_t& lw1) {
    __nv_bfloat162 h0 = __floats2bfloat162_rn(v.x, v.y);
    __nv_bfloat162 h1 = __floats2bfloat162_rn(v.z, v.w);
    float lx = v.x - __bfloat162float(h0.x);
    float ly = v.y - __bfloat162float(h0.y);
    float lz = v.z - __bfloat162float(h1.x);
    float lw = v.w - __bfloat162float(h1.y);
    __nv_bfloat162 l0 = __floats2bfloat162_rn(lx, ly);
    __nv_bfloat162 l1 = __floats2bfloat162_rn(lz, lw);
    hw0 = *(uint32_t*)&h0; hw1 = *(uint32_t*)&h1;
    lw0 = *(uint32_t*)&l0; lw1 = *(uint32_t*)&l1;
}

__global__ __launch_bounds__(256, 3)
void mb_scores_kernel(const float* __restrict__ q,
                      const float* __restrict__ k,
                      const int*   __restrict__ bseq,
                      float* __restrict__ out) {
    extern __shared__ unsigned char smraw[];
    float* Qs = (float*)(smraw + OFF_Q);
    unsigned char* Ab = smraw + OFF_A;
    unsigned char* Bb = smraw + OFF_B;
    int* bj_all = (int*)(smraw + OFF_INT);
    int* jperm  = bj_all + 512;
    int* rlist  = jperm + 512;
    int* jcnt   = rlist + 256;
    int* joff   = jcnt + 8;
    int* jpos   = joff + 8;
    int* rcnt   = jpos + 8;
    int* cls    = rcnt + 8;
    int* coff   = cls + MAXCH;
    int* clen   = coff + MAXCH;
    int* nchS   = clen + MAXCH;

    const int tid = threadIdx.x;
    const int wid = tid >> 5;
    const int lid = tid & 31;
    const int it  = blockIdx.x;
    const int h   = blockIdx.y;
    const int b   = blockIdx.z;
    const int i0  = it * TI;

    const float* qbase = q + ((size_t)(b * HNUM + h) * SLEN + i0) * DDIM;
    const float* kbase = k + ((size_t)(b * HNUM + h) * SLEN) * DDIM;

    for (int t = tid; t < TI * DDIM / 4; t += 256)
        ((float4*)Qs)[t] = ((const float4*)qbase)[t];
    for (int t = tid; t < SLEN; t += 256) bj_all[t] = bseq[b * SLEN + t];
    if (tid < 8) { jcnt[tid] = 0; rcnt[tid] = 0; }
    __syncthreads();

    for (int t = tid; t < SLEN; t += 256) atomicAdd(&jcnt[bj_all[t]], 1);
    __syncthreads();
    if (tid == 0) {
        int s = 0;
        for (int t = 0; t < 5; t++) { joff[t] = s; jpos[t] = s; s += jcnt[t]; }
        int nc = 0;
        for (int t = 0; t < 5; t++) {
            int nt = jcnt[t], off = joff[t];
            for (int j0 = 0; j0 < nt; j0 += JT) {
                cls[nc] = t; coff[nc] = off + j0;
                clen[nc] = (nt - j0 < JT) ? (nt - j0) : JT;
                nc++;
            }
        }
        nchS[0] = nc;
    }
    __syncthreads();
    for (int t = tid; t < SLEN; t += 256) {
        int c = bj_all[t];
        int p = atomicAdd(&jpos[c], 1);
        jperm[p] = t;
    }
    for (int t = tid; t < TI; t += 256) {
        int c = bj_all[i0 + t];
        if (c > 0) { int p = atomicAdd(&rcnt[c - 1], 1); rlist[(c - 1) * 64 + p] = t; }
    }
    __syncthreads();

    const int ncls = nchS[0];
    const int n = tid & 63;
    const int g = tid >> 6;   // 0..3

    // ---- Phase A0: slot0 for all 64 rows ----
    {
        const float* W0 = g_W + (size_t)h * DDIM * DDIM + n;   // c=0
        for (int r = 0; r < 16; r += 2)
            urow2(Qs, Ab, W0, g * 16 + r, g * 16 + r + 1, n);
    }
    __syncthreads();   // A0 complete before any cross-group rewrite

    // ---- per-warp ldmatrix lane addressing ----
    const uint32_t smem_base = (uint32_t)__cvta_generic_to_shared(smraw);
    const int wr = (wid >> 2) * 32;        // warp row base (0/32)
    const int wc = (wid & 3) * 32;         // warp col base (0/32/64/96)
    uint32_t aAddr0 = smem_base + OFF_A +
        (uint32_t)(((wr + (lid & 15)) * AST + ((lid & 16) ? 8 : 0)) * 2);
    uint32_t aAddr1 = aAddr0 + 16 * AST * 2;
    uint32_t bAddr0 = smem_base + OFF_B +
        (uint32_t)(((wc + (lid & 7) + ((lid & 16) ? 8 : 0)) * BST + ((lid & 8) ? 8 : 0)) * 2);
    uint32_t bAddr1 = bAddr0 + 16 * BST * 2;

    float* outbase = out + ((size_t)(b * HNUM + h) * SLEN + i0) * SLEN;

    int prevClass = 0;
    for (int c = 0; c < ncls; c++) {
        const int t   = cls[c];
        const int len = clen[c];
        const int off = coff[c];

        // class transition: rewrite A' rows with bi>0 for class t
        if (t > 0 && t != prevClass) {
            int v = g + 1;
            int cnt = rcnt[v - 1];
            if (cnt > 0) {
                int cc = 4 * (v - 1) + t;
                const float* Wc = g_W + (size_t)(cc * HNUM + h) * DDIM * DDIM + n;
                int r = 0;
                for (; r + 1 < cnt; r += 2)
                    urow2(Qs, Ab, Wc, rlist[(v - 1) * 64 + r],
                          rlist[(v - 1) * 64 + r + 1], n);
                if (r < cnt)
                    urow2(Qs, Ab, Wc, rlist[(v - 1) * 64 + r],
                          rlist[(v - 1) * 64 + r], n);
            }
            prevClass = t;
        }

        // ---- convert K chunk -> B' slices [KH | KL] ----
        {
            int j2 = tid >> 1, half = tid & 1;
            if (j2 < len) {
                int jp = jperm[off + j2];
                const float4* src = (const float4*)(kbase + (size_t)jp * DDIM + half * 32);
#pragma unroll
                for (int qd = 0; qd < 8; qd++) {
                    float4 v = src[qd];
                    uint32_t hw0, hw1, lw0, lw1;
                    cvt4(v, hw0, hw1, lw0, lw1);
                    uint32_t byt = (uint32_t)(j2 * BST + half * 32 + qd * 4) * 2;
                    *(uint32_t*)(Bb + byt)       = hw0;
                    *(uint32_t*)(Bb + byt + 4)   = hw1;
                    *(uint32_t*)(Bb + byt + 128) = lw0;   // KL slice (cols +64)
                    *(uint32_t*)(Bb + byt + 132) = lw1;
                }
            }
        }
        __syncthreads();   // A' + B' visible

        // ---- HMMA mainloop: 3 terms (UH·KH, UH·KL, UL·KH) x 4 k-steps ----
        float d[2][4][4];
#pragma unroll
        for (int mt = 0; mt < 2; mt++)
#pragma unroll
            for (int n8 = 0; n8 < 4; n8++)
#pragma unroll
                for (int e = 0; e < 4; e++) d[mt][n8][e] = 0.f;

#pragma unroll
        for (int s = 0; s < 3; s++) {
            const uint32_t aOff = (s == 2) ? 128u : 0u;   // UL slice
            const uint32_t bOff = (s == 1) ? 128u : 0u;   // KL slice
#pragma unroll
            for (int ks = 0; ks < 4; ks++) {
                uint32_t a0[4], a1[4], b0[4], b1[4];
                LDSM4(a0, aAddr0 + aOff + ks * 32);
                LDSM4(a1, aAddr1 + aOff + ks * 32);
                LDSM4(b0, bAddr0 + bOff + ks * 32);
                LDSM4(b1, bAddr1 + bOff + ks * 32);
                MMA16816(d[0][0], a0, b0[0], b0[1]);
                MMA16816(d[0][1], a0, b0[2], b0[3]);
                MMA16816(d[0][2], a0, b1[0], b1[1]);
                MMA16816(d[0][3], a0, b1[2], b1[3]);
                MMA16816(d[1][0], a1, b0[0], b0[1]);
                MMA16816(d[1][1], a1, b0[2], b0[3]);
                MMA16816(d[1][2], a1, b1[0], b1[1]);
                MMA16816(d[1][3], a1, b1[2], b1[3]);
            }
        }

        // ---- epilogue: fragments -> scattered global stores via jperm ----
        {
            int rbase = wr + (lid >> 2);
            int cb    = wc + (lid & 3) * 2;
#pragma unroll
            for (int n8 = 0; n8 < 4; n8++) {
                int col = cb + n8 * 8;
                if (col < len) {
                    int jp = jperm[off + col];
#pragma unroll
                    for (int mt = 0; mt < 2; mt++) {
                        int row = rbase + mt * 16;
                        outbase[(size_t)row * SLEN + jp]       = d[mt][n8][0];
                        outbase[(size_t)(row + 8) * SLEN + jp] = d[mt][n8][2];
                    }
                }
                if (col + 1 < len) {
                    int jp = jperm[off + col + 1];
#pragma unroll
                    for (int mt = 0; mt < 2; mt++) {
                        int row = rbase + mt * 16;
                        outbase[(size_t)row * SLEN + jp]       = d[mt][n8][1];
                        outbase[(size_t)(row + 8) * SLEN + jp] = d[mt][n8][3];
                    }
                }
            }
        }
        __syncthreads();   // all reads of A'/B' done before next chunk overwrites
    }
}

// ---------------- launch ----------------
extern "C" void kernel_launch(void* const* d_in, const int* in_sizes, int n_in,
                              void* d_out, int out_size) {
    const float* q      = (const float*)d_in[0];
    const float* kk     = (const float*)d_in[1];
    const int*   bseq   = (const int*)  d_in[2];
    const float* W1     = (const float*)d_in[3];
    const float* alpha1 = (const float*)d_in[4];
    float* out = (float*)d_out;

    cudaFuncSetAttribute(mb_scores_kernel,
                         cudaFuncAttributeMaxDynamicSharedMemorySize, SMEM_BYTES);

    dim3 g1(CNUM, HNUM);
    wmix_kernel<<<g1, 256>>>(W1, alpha1);

    dim3 g2(SLEN / TI, HNUM, BNUM);   // 512 blocks
    mb_scores_kernel<<<g2, 256, SMEM_BYTES>>>(q, kk, bseq, out);
}

// round 12
// speedup vs baseline: 1.2345x; 1.2345x over previous
#include <cuda_runtime.h>
#include <cuda_bf16.h>
#include <stdint.h>

#define NMB  4
#define CNUM 17
#define HNUM 8
#define BNUM 8
#define SLEN 512
#define DDIM 64
#define TI   64
#define JT   128
#define MAXCH 12
#define AST  136   // A' row stride (bf16): 272B -> conflict-free ldmatrix
#define BST  136   // B' row stride (bf16)
#define BUFB (JT * BST * 2)   // one B' buffer: 34816 B

// Premixed W1_: [C][h][m][n]  (n-major: lane-coalesced reads)
__device__ float g_W[CNUM * HNUM * DDIM * DDIM];

// ---- packed f32x2 helpers (phase A) ----
union F4U   { float4 f4; unsigned long long u[2]; };
union U64F2 { unsigned long long u; float2 f; };
__device__ __forceinline__ void ffma2(unsigned long long& d,
                                      unsigned long long a,
                                      unsigned long long b) {
    asm("fma.rn.f32x2 %0, %1, %2, %0;" : "+l"(d) : "l"(a), "l"(b));
}
__device__ __forceinline__ unsigned long long pack2(float x, float y) {
    unsigned long long r;
    asm("mov.b64 %0, {%1, %2};" : "=l"(r) : "f"(x), "f"(y));
    return r;
}
__device__ __forceinline__ float hadd2(unsigned long long a) {
    U64F2 x; x.u = a; return x.f.x + x.f.y;
}

// ---- HMMA helpers ----
#define LDSM4(r, a) \
    asm volatile("ldmatrix.sync.aligned.m8n8.x4.shared.b16 {%0,%1,%2,%3}, [%4];" \
        : "=r"((r)[0]), "=r"((r)[1]), "=r"((r)[2]), "=r"((r)[3]) : "r"(a))

#define MMA16816(d, a, b0v, b1v) \
    asm volatile("mma.sync.aligned.m16n8k16.row.col.f32.bf16.bf16.f32 " \
        "{%0,%1,%2,%3}, {%4,%5,%6,%7}, {%8,%9}, {%0,%1,%2,%3};" \
        : "+f"((d)[0]), "+f"((d)[1]), "+f"((d)[2]), "+f"((d)[3]) \
        : "r"((a)[0]), "r"((a)[1]), "r"((a)[2]), "r"((a)[3]), "r"(b0v), "r"(b1v))

// ---------------- Kernel 1: premix W ----------------
__global__ void wmix_kernel(const float* __restrict__ W1,
                            const float* __restrict__ alpha1) {
    int c = blockIdx.x, h = blockIdx.y;
    float a[NMB];
#pragma unroll
    for (int B = 0; B < NMB; B++) a[B] = alpha1[(c * NMB + B) * HNUM + h];
    float mx = fmaxf(fmaxf(a[0], a[1]), fmaxf(a[2], a[3]));
    float w[NMB], s = 0.f;
#pragma unroll
    for (int B = 0; B < NMB; B++) { w[B] = __expf(a[B] - mx); s += w[B]; }
    float inv = 1.f / s;
#pragma unroll
    for (int B = 0; B < NMB; B++) w[B] *= inv;
    float* dst = g_W + (c * HNUM + h) * DDIM * DDIM;
    const float* src = W1 + h * DDIM * DDIM;
    for (int e = threadIdx.x; e < DDIM * DDIM; e += blockDim.x) {
        float v = 0.f;
#pragma unroll
        for (int B = 0; B < NMB; B++) v += w[B] * src[B * HNUM * DDIM * DDIM + e];
        dst[e] = v;
    }
}

// ---------------- shared layout (bytes) ----------------
#define OFF_Q    0                     // 16384
#define OFF_A    16384                 // 17408
#define OFF_B    (16384 + 17408)       // 2 * 34816 = 69632
#define OFF_INT  (OFF_B + 2 * BUFB)
#define NINTS (512 + 512 + 256 + 8 + 8 + 8 + 8 + MAXCH * 3 + 4)
#define SMEM_BYTES (OFF_INT + NINTS * 4)

// phase-A row: U fp32 -> bf16 hi/lo into A' slices [UH | UL]  (R10-proven)
__device__ __forceinline__ void urow(const float* Qs, unsigned char* Ab,
                                     const unsigned long long* wp, int i, int n) {
    const F4U* qa = (const F4U*)(Qs + i * DDIM);
    unsigned long long a0 = 0, a1 = 0;
#pragma unroll
    for (int mb = 0; mb < 16; mb++) {
        F4U v = qa[mb];
        ffma2(a0, v.u[0], wp[2 * mb]);
        ffma2(a1, v.u[1], wp[2 * mb + 1]);
    }
    float u = hadd2(a0) + hadd2(a1);
    __nv_bfloat16 hi = __float2bfloat16(u);
    __nv_bfloat16 lo = __float2bfloat16(u - __bfloat162float(hi));
    uint32_t o = (uint32_t)(i * AST + n) * 2;
    *(__nv_bfloat16*)(Ab + o)       = hi;
    *(__nv_bfloat16*)(Ab + o + 128) = lo;
}

__device__ __forceinline__ void cvt4(float4 v, uint32_t& hw0, uint32_t& hw1,
                                     uint32_t& lw0, uint32_t& lw1) {
    __nv_bfloat162 h0 = __floats2bfloat162_rn(v.x, v.y);
    __nv_bfloat162 h1 = __floats2bfloat162_rn(v.z, v.w);
    float lx = v.x - __bfloat162float(h0.x);
    float ly = v.y - __bfloat162float(h0.y);
    float lz = v.z - __bfloat162float(h1.x);
    float lw = v.w - __bfloat162float(h1.y);
    __nv_bfloat162 l0 = __floats2bfloat162_rn(lx, ly);
    __nv_bfloat162 l1 = __floats2bfloat162_rn(lz, lw);
    hw0 = *(uint32_t*)&h0; hw1 = *(uint32_t*)&h1;
    lw0 = *(uint32_t*)&l0; lw1 = *(uint32_t*)&l1;
}

// cvt + STS of a held K chunk (j2/half fixed per thread)
__device__ __forceinline__ void sts_chunk(unsigned char* Bbuf, const float4* kv,
                                          int j2, int half, bool valid) {
    if (!valid) return;
#pragma unroll
    for (int qd = 0; qd < 8; qd++) {
        uint32_t hw0, hw1, lw0, lw1;
        cvt4(kv[qd], hw0, hw1, lw0, lw1);
        uint32_t byt = (uint32_t)(j2 * BST + half * 32 + qd * 4) * 2;
        *(uint32_t*)(Bbuf + byt)       = hw0;
        *(uint32_t*)(Bbuf + byt + 4)   = hw1;
        *(uint32_t*)(Bbuf + byt + 128) = lw0;   // KL slice (cols +64)
        *(uint32_t*)(Bbuf + byt + 132) = lw1;
    }
}

__global__ __launch_bounds__(256, 2)
void mb_scores_kernel(const float* __restrict__ q,
                      const float* __restrict__ k,
                      const int*   __restrict__ bseq,
                      float* __restrict__ out) {
    extern __shared__ unsigned char smraw[];
    float* Qs = (float*)(smraw + OFF_Q);
    unsigned char* Ab = smraw + OFF_A;
    unsigned char* Bb = smraw + OFF_B;
    int* bj_all = (int*)(smraw + OFF_INT);
    int* jperm  = bj_all + 512;
    int* rlist  = jperm + 512;
    int* jcnt   = rlist + 256;
    int* joff   = jcnt + 8;
    int* jpos   = joff + 8;
    int* rcnt   = jpos + 8;
    int* cls    = rcnt + 8;
    int* coff   = cls + MAXCH;
    int* clen   = coff + MAXCH;
    int* nchS   = clen + MAXCH;

    const int tid = threadIdx.x;
    const int wid = tid >> 5;
    const int lid = tid & 31;
    const int it  = blockIdx.x;
    const int h   = blockIdx.y;
    const int b   = blockIdx.z;
    const int i0  = it * TI;

    const float* qbase = q + ((size_t)(b * HNUM + h) * SLEN + i0) * DDIM;
    const float* kbase = k + ((size_t)(b * HNUM + h) * SLEN) * DDIM;

    for (int t = tid; t < TI * DDIM / 4; t += 256)
        ((float4*)Qs)[t] = ((const float4*)qbase)[t];
    for (int t = tid; t < SLEN; t += 256) bj_all[t] = bseq[b * SLEN + t];
    if (tid < 8) { jcnt[tid] = 0; rcnt[tid] = 0; }
    __syncthreads();

    for (int t = tid; t < SLEN; t += 256) atomicAdd(&jcnt[bj_all[t]], 1);
    __syncthreads();
    if (tid == 0) {
        int s = 0;
        for (int t = 0; t < 5; t++) { joff[t] = s; jpos[t] = s; s += jcnt[t]; }
        int nc = 0;
        for (int t = 0; t < 5; t++) {
            int nt = jcnt[t], off = joff[t];
            for (int j0 = 0; j0 < nt; j0 += JT) {
                cls[nc] = t; coff[nc] = off + j0;
                clen[nc] = (nt - j0 < JT) ? (nt - j0) : JT;
                nc++;
            }
        }
        nchS[0] = nc;
    }
    __syncthreads();
    for (int t = tid; t < SLEN; t += 256) {
        int c = bj_all[t];
        int p = atomicAdd(&jpos[c], 1);
        jperm[p] = t;
    }
    for (int t = tid; t < TI; t += 256) {
        int c = bj_all[i0 + t];
        if (c > 0) { int p = atomicAdd(&rcnt[c - 1], 1); rlist[(c - 1) * 64 + p] = t; }
    }
    __syncthreads();

    const int ncls = nchS[0];
    const int n = tid & 63;
    const int g = tid >> 6;   // 0..3
    const int j2 = tid >> 1, half = tid & 1;   // convert-lane mapping

    // ---- Phase A0: slot0 for all 64 rows (wp[32], R10-proven) ----
    {
        const float* W0 = g_W + (size_t)h * DDIM * DDIM + n;   // c=0
        unsigned long long wp[32];
#pragma unroll
        for (int m2 = 0; m2 < 32; m2++)
            wp[m2] = pack2(W0[(2 * m2) * DDIM], W0[(2 * m2 + 1) * DDIM]);
        for (int r = 0; r < 16; r += 2) {
            urow(Qs, Ab, wp, g * 16 + r, n);
            urow(Qs, Ab, wp, g * 16 + r + 1, n);
        }
    }

    // ---- prologue: full convert of chunk 0 into buf0 ----
    {
        int len0 = clen[0], off0 = coff[0];
        bool v = j2 < len0;
        float4 kv[8];
        const float4* src = (const float4*)(kbase +
            (size_t)(v ? jperm[off0 + j2] : 0) * DDIM + half * 32);
#pragma unroll
        for (int qd = 0; qd < 8; qd++)
            kv[qd] = v ? src[qd] : make_float4(0.f, 0.f, 0.f, 0.f);
        sts_chunk(Bb, kv, j2, half, v);
    }
    __syncthreads();   // A0 + buf0 ready

    // ---- per-warp ldmatrix lane addressing ----
    const uint32_t smem_base = (uint32_t)__cvta_generic_to_shared(smraw);
    const int wr = (wid >> 2) * 32;
    const int wc = (wid & 3) * 32;
    uint32_t aAddr0 = smem_base + OFF_A +
        (uint32_t)(((wr + (lid & 15)) * AST + ((lid & 16) ? 8 : 0)) * 2);
    uint32_t aAddr1 = aAddr0 + 16 * AST * 2;
    uint32_t bAddrBase0 = smem_base + OFF_B +
        (uint32_t)(((wc + (lid & 7) + ((lid & 16) ? 8 : 0)) * BST + ((lid & 8) ? 8 : 0)) * 2);

    float* outbase = out + ((size_t)(b * HNUM + h) * SLEN + i0) * SLEN;

    int prevClass = 0;
    for (int c = 0; c < ncls; c++) {
        const int t   = cls[c];
        const int len = clen[c];
        const int off = coff[c];

        // class transition: rewrite A' rows with bi>0 (prior MMA done via trailing bar)
        if (t > 0 && t != prevClass) {
            int v = g + 1;
            int cnt = rcnt[v - 1];
            if (cnt > 0) {
                int cc = 4 * (v - 1) + t;
                const float* Wc = g_W + (size_t)(cc * HNUM + h) * DDIM * DDIM + n;
                unsigned long long wp[32];
#pragma unroll
                for (int m2 = 0; m2 < 32; m2++)
                    wp[m2] = pack2(Wc[(2 * m2) * DDIM], Wc[(2 * m2 + 1) * DDIM]);
                int r = 0;
                for (; r + 1 < cnt; r += 2) {
                    urow(Qs, Ab, wp, rlist[(v - 1) * 64 + r], n);
                    urow(Qs, Ab, wp, rlist[(v - 1) * 64 + r + 1], n);
                }
                if (r < cnt) urow(Qs, Ab, wp, rlist[(v - 1) * 64 + r], n);
            }
            prevClass = t;
            __syncthreads();   // A visible before MMA(c)
        }

        // ---- LDG chunk c+1 into registers (hidden under MMA below) ----
        float4 kv[8];
        bool vN = false;
        if (c + 1 < ncls) {
            int lenN = clen[c + 1], offN = coff[c + 1];
            vN = j2 < lenN;
            const float4* src = (const float4*)(kbase +
                (size_t)(vN ? jperm[offN + j2] : 0) * DDIM + half * 32);
#pragma unroll
            for (int qd = 0; qd < 8; qd++)
                kv[qd] = vN ? src[qd] : make_float4(0.f, 0.f, 0.f, 0.f);
        }

        // ---- HMMA mainloop on buf[c&1]: 3 terms x 4 k-steps ----
        const uint32_t bAddr0 = bAddrBase0 + (uint32_t)(c & 1) * BUFB;
        const uint32_t bAddr1 = bAddr0 + 16 * BST * 2;
        float d[2][4][4];
#pragma unroll
        for (int mt = 0; mt < 2; mt++)
#pragma unroll
            for (int n8 = 0; n8 < 4; n8++)
#pragma unroll
                for (int e = 0; e < 4; e++) d[mt][n8][e] = 0.f;

#pragma unroll
        for (int s = 0; s < 3; s++) {
            const uint32_t aOff = (s == 2) ? 128u : 0u;
            const uint32_t bOff = (s == 1) ? 128u : 0u;
#pragma unroll
            for (int ks = 0; ks < 4; ks++) {
                uint32_t a0[4], a1[4], b0[4], b1[4];
                LDSM4(a0, aAddr0 + aOff + ks * 32);
                LDSM4(a1, aAddr1 + aOff + ks * 32);
                LDSM4(b0, bAddr0 + bOff + ks * 32);
                LDSM4(b1, bAddr1 + bOff + ks * 32);
                MMA16816(d[0][0], a0, b0[0], b0[1]);
                MMA16816(d[0][1], a0, b0[2], b0[3]);
                MMA16816(d[0][2], a0, b1[0], b1[1]);
                MMA16816(d[0][3], a0, b1[2], b1[3]);
                MMA16816(d[1][0], a1, b0[0], b0[1]);
                MMA16816(d[1][1], a1, b0[2], b0[3]);
                MMA16816(d[1][2], a1, b1[0], b1[1]);
                MMA16816(d[1][3], a1, b1[2], b1[3]);
            }
        }

        // ---- epilogue: fragments -> scattered global stores via jperm ----
        {
            int rbase = wr + (lid >> 2);
            int cb    = wc + (lid & 3) * 2;
#pragma unroll
            for (int n8 = 0; n8 < 4; n8++) {
                int col = cb + n8 * 8;
                if (col < len) {
                    int jp = jperm[off + col];
#pragma unroll
                    for (int mt = 0; mt < 2; mt++) {
                        int row = rbase + mt * 16;
                        outbase[(size_t)row * SLEN + jp]       = d[mt][n8][0];
                        outbase[(size_t)(row + 8) * SLEN + jp] = d[mt][n8][2];
                    }
                }
                if (col + 1 < len) {
                    int jp = jperm[off + col + 1];
#pragma unroll
                    for (int mt = 0; mt < 2; mt++) {
                        int row = rbase + mt * 16;
                        outbase[(size_t)row * SLEN + jp]       = d[mt][n8][1];
                        outbase[(size_t)(row + 8) * SLEN + jp] = d[mt][n8][3];
                    }
                }
            }
        }

        // ---- cvt + STS of chunk c+1 into buf[(c+1)&1], then ONE barrier ----
        if (c + 1 < ncls)
            sts_chunk(Bb + (uint32_t)((c + 1) & 1) * BUFB, kv, j2, half, vN);
        __syncthreads();
    }
}

// ---------------- launch ----------------
extern "C" void kernel_launch(void* const* d_in, const int* in_sizes, int n_in,
                              void* d_out, int out_size) {
    const float* q      = (const float*)d_in[0];
    const float* kk     = (const float*)d_in[1];
    const int*   bseq   = (const int*)  d_in[2];
    const float* W1     = (const float*)d_in[3];
    const float* alpha1 = (const float*)d_in[4];
    float* out = (float*)d_out;

    cudaFuncSetAttribute(mb_scores_kernel,
                         cudaFuncAttributeMaxDynamicSharedMemorySize, SMEM_BYTES);

    dim3 g1(CNUM, HNUM);
    wmix_kernel<<<g1, 256>>>(W1, alpha1);

    dim3 g2(SLEN / TI, HNUM, BNUM);   // 512 blocks
    mb_scores_kernel<<<g2, 256, SMEM_BYTES>>>(q, kk, bseq, out);
}

// round 14
// speedup vs baseline: 1.5918x; 1.2895x over previous
#include <cuda_runtime.h>
#include <cuda_bf16.h>
#include <stdint.h>

#define NMB  4
#define CNUM 17
#define HNUM 8
#define BNUM 8
#define SLEN 512
#define DDIM 64
#define TI   32
#define JT   64
#define MAXCH 16
#define AST  136      // A' row stride (bf16)
#define BST  136      // B' row stride (bf16)
#define OSTR 516      // OUT smem row stride (floats); 516%32=4 -> spread banks

// Premixed W1_: [C][h][m][n]  (n-major: lane-coalesced reads)
__device__ float g_W[CNUM * HNUM * DDIM * DDIM];
// Pre-split K: bf16 hi/lo, [b,h,S,d]
__device__ __nv_bfloat16 g_Khi[BNUM * HNUM * SLEN * DDIM];
__device__ __nv_bfloat16 g_Klo[BNUM * HNUM * SLEN * DDIM];

// ---- packed f32x2 helpers (phase A) ----
union F4U   { float4 f4; unsigned long long u[2]; };
union U64F2 { unsigned long long u; float2 f; };
__device__ __forceinline__ void ffma2(unsigned long long& d,
                                      unsigned long long a,
                                      unsigned long long b) {
    asm("fma.rn.f32x2 %0, %1, %2, %0;" : "+l"(d) : "l"(a), "l"(b));
}
__device__ __forceinline__ unsigned long long pack2(float x, float y) {
    unsigned long long r;
    asm("mov.b64 %0, {%1, %2};" : "=l"(r) : "f"(x), "f"(y));
    return r;
}
__device__ __forceinline__ float hadd2(unsigned long long a) {
    U64F2 x; x.u = a; return x.f.x + x.f.y;
}

// ---- HMMA helpers ----
#define LDSM4(r, a) \
    asm volatile("ldmatrix.sync.aligned.m8n8.x4.shared.b16 {%0,%1,%2,%3}, [%4];" \
        : "=r"((r)[0]), "=r"((r)[1]), "=r"((r)[2]), "=r"((r)[3]) : "r"(a))

#define MMA16816(d, a, b0v, b1v) \
    asm volatile("mma.sync.aligned.m16n8k16.row.col.f32.bf16.bf16.f32 " \
        "{%0,%1,%2,%3}, {%4,%5,%6,%7}, {%8,%9}, {%0,%1,%2,%3};" \
        : "+f"((d)[0]), "+f"((d)[1]), "+f"((d)[2]), "+f"((d)[3]) \
        : "r"((a)[0]), "r"((a)[1]), "r"((a)[2]), "r"((a)[3]), "r"(b0v), "r"(b1v))

// ---------------- Kernel 1: premix W ----------------
__global__ void wmix_kernel(const float* __restrict__ W1,
                            const float* __restrict__ alpha1) {
    int c = blockIdx.x, h = blockIdx.y;
    float a[NMB];
#pragma unroll
    for (int B = 0; B < NMB; B++) a[B] = alpha1[(c * NMB + B) * HNUM + h];
    float mx = fmaxf(fmaxf(a[0], a[1]), fmaxf(a[2], a[3]));
    float w[NMB], s = 0.f;
#pragma unroll
    for (int B = 0; B < NMB; B++) { w[B] = __expf(a[B] - mx); s += w[B]; }
    float inv = 1.f / s;
#pragma unroll
    for (int B = 0; B < NMB; B++) w[B] *= inv;
    float* dst = g_W + (c * HNUM + h) * DDIM * DDIM;
    const float* src = W1 + h * DDIM * DDIM;
    for (int e = threadIdx.x; e < DDIM * DDIM; e += blockDim.x) {
        float v = 0.f;
#pragma unroll
        for (int B = 0; B < NMB; B++) v += w[B] * src[B * HNUM * DDIM * DDIM + e];
        dst[e] = v;
    }
}

// ---------------- Kernel 2: pre-split K into bf16 hi/lo ----------------
__global__ void ksplit_kernel(const float* __restrict__ k) {
    int idx = blockIdx.x * 256 + threadIdx.x;   // float4 index
    float4 v = ((const float4*)k)[idx];
    __nv_bfloat162 h0 = __floats2bfloat162_rn(v.x, v.y);
    __nv_bfloat162 h1 = __floats2bfloat162_rn(v.z, v.w);
    __nv_bfloat162 l0 = __floats2bfloat162_rn(v.x - __bfloat162float(h0.x),
                                              v.y - __bfloat162float(h0.y));
    __nv_bfloat162 l1 = __floats2bfloat162_rn(v.z - __bfloat162float(h1.x),
                                              v.w - __bfloat162float(h1.y));
    uint2 hw, lw;
    hw.x = *(uint32_t*)&h0; hw.y = *(uint32_t*)&h1;
    lw.x = *(uint32_t*)&l0; lw.y = *(uint32_t*)&l1;
    ((uint2*)g_Khi)[idx] = hw;
    ((uint2*)g_Klo)[idx] = lw;
}

// ---------------- shared layout (bytes) ----------------
#define OFF_Q    0                          // 32*64*4   = 8192
#define OFF_A    8192                       // 32*136*2  = 8704
#define OFF_B    (8192 + 8704)              // 64*136*2  = 17408
#define OFF_OUT  (OFF_B + 17408)            // 32*516*4  = 66048
#define OFF_INT  (OFF_OUT + 66048)
// ints: bj_all[512] jperm[512] rlist[128] jcnt8 joff8 jpos8 rcnt8 cls16 coff16 clen16 nch4
#define NINTS (512 + 512 + 128 + 8 + 8 + 8 + 8 + MAXCH * 3 + 4)
#define SMEM_BYTES (OFF_INT + NINTS * 4)

// phase-A row: U fp32 -> bf16 hi/lo into A' slices [UH | UL]
__device__ __forceinline__ void urow(const float* Qs, unsigned char* Ab,
                                     const unsigned long long* wp, int i, int n) {
    const F4U* qa = (const F4U*)(Qs + i * DDIM);
    unsigned long long a0 = 0, a1 = 0;
#pragma unroll
    for (int mb = 0; mb < 16; mb++) {
        F4U v = qa[mb];
        ffma2(a0, v.u[0], wp[2 * mb]);
        ffma2(a1, v.u[1], wp[2 * mb + 1]);
    }
    float u = hadd2(a0) + hadd2(a1);
    __nv_bfloat16 hi = __float2bfloat16(u);
    __nv_bfloat16 lo = __float2bfloat16(u - __bfloat162float(hi));
    uint32_t o = (uint32_t)(i * AST + n) * 2;
    *(__nv_bfloat16*)(Ab + o)       = hi;
    *(__nv_bfloat16*)(Ab + o + 128) = lo;
}

__global__ __launch_bounds__(256, 2)
void mb_scores_kernel(const float* __restrict__ q,
                      const int*   __restrict__ bseq,
                      float* __restrict__ out) {
    extern __shared__ unsigned char smraw[];
    float* Qs = (float*)(smraw + OFF_Q);
    unsigned char* Ab = smraw + OFF_A;
    unsigned char* Bb = smraw + OFF_B;
    float* OUT = (float*)(smraw + OFF_OUT);
    int* bj_all = (int*)(smraw + OFF_INT);
    int* jperm  = bj_all + 512;
    int* rlist  = jperm + 512;
    int* jcnt   = rlist + 128;
    int* joff   = jcnt + 8;
    int* jpos   = joff + 8;
    int* rcnt   = jpos + 8;
    int* cls    = rcnt + 8;
    int* coff   = cls + MAXCH;
    int* clen   = coff + MAXCH;
    int* nchS   = clen + MAXCH;

    const int tid = threadIdx.x;
    const int wid = tid >> 5;
    const int lid = tid & 31;
    const int it  = blockIdx.x;
    const int h   = blockIdx.y;
    const int b   = blockIdx.z;
    const int i0  = it * TI;
    const int bh  = b * HNUM + h;

    const float* qbase = q + ((size_t)bh * SLEN + i0) * DDIM;
    const __nv_bfloat16* khbase = g_Khi + (size_t)bh * SLEN * DDIM;
    const __nv_bfloat16* klbase = g_Klo + (size_t)bh * SLEN * DDIM;

    for (int t = tid; t < TI * DDIM / 4; t += 256)
        ((float4*)Qs)[t] = ((const float4*)qbase)[t];
    for (int t = tid; t < SLEN; t += 256) bj_all[t] = bseq[b * SLEN + t];
    if (tid < 8) { jcnt[tid] = 0; rcnt[tid] = 0; }
    __syncthreads();

    for (int t = tid; t < SLEN; t += 256) atomicAdd(&jcnt[bj_all[t]], 1);
    __syncthreads();
    if (tid == 0) {
        int s = 0;
        for (int t = 0; t < 5; t++) { joff[t] = s; jpos[t] = s; s += jcnt[t]; }
        int nc = 0;
        for (int t = 0; t < 5; t++) {
            int nt = jcnt[t], off = joff[t];
            for (int j0 = 0; j0 < nt; j0 += JT) {
                cls[nc] = t; coff[nc] = off + j0;
                clen[nc] = (nt - j0 < JT) ? (nt - j0) : JT;
                nc++;
            }
        }
        nchS[0] = nc;
    }
    __syncthreads();
    for (int t = tid; t < SLEN; t += 256) {
        int c = bj_all[t];
        int p = atomicAdd(&jpos[c], 1);
        jperm[p] = t;
    }
    for (int t = tid; t < TI; t += 256) {
        int c = bj_all[i0 + t];
        if (c > 0) { int p = atomicAdd(&rcnt[c - 1], 1); rlist[(c - 1) * 32 + p] = t; }
    }
    __syncthreads();

    const int ncls = nchS[0];
    const int n = tid & 63;
    const int g = tid >> 6;              // 0..3
    const int j2 = tid >> 2, qq = tid & 3;   // convert mapping: row j2, 16-elem quarter qq

    // ---- Phase A0: slot0 for all 32 rows (wp[32], proven) ----
    {
        const float* W0 = g_W + (size_t)h * DDIM * DDIM + n;   // c=0
        unsigned long long wp[32];
#pragma unroll
        for (int m2 = 0; m2 < 32; m2++)
            wp[m2] = pack2(W0[(2 * m2) * DDIM], W0[(2 * m2 + 1) * DDIM]);
        for (int r = 0; r < 8; r += 2) {
            urow(Qs, Ab, wp, g * 8 + r, n);
            urow(Qs, Ab, wp, g * 8 + r + 1, n);
        }
    }

    // ---- prologue: copy chunk 0 K hi/lo into B' ----
    {
        int len0 = clen[0], off0 = coff[0];
        uint4 h0, h1, l0, l1;
        if (j2 < len0) {
            int jp = jperm[off0 + j2];
            const uint4* sh = (const uint4*)(khbase + (size_t)jp * DDIM + qq * 16);
            const uint4* sl = (const uint4*)(klbase + (size_t)jp * DDIM + qq * 16);
            h0 = sh[0]; h1 = sh[1]; l0 = sl[0]; l1 = sl[1];
        } else {
            h0 = h1 = l0 = l1 = make_uint4(0, 0, 0, 0);
        }
        uint32_t byt = (uint32_t)(j2 * BST + qq * 16) * 2;
        *(uint4*)(Bb + byt)        = h0;
        *(uint4*)(Bb + byt + 16)   = h1;
        *(uint4*)(Bb + byt + 128)  = l0;   // lo slice: +64 elems = +128B
        *(uint4*)(Bb + byt + 144)  = l1;
    }
    __syncthreads();   // A0 + B'(chunk0) ready

    // ---- per-warp ldmatrix lane addressing (warp grid 2x4, tile 16x16) ----
    const uint32_t smem_base = (uint32_t)__cvta_generic_to_shared(smraw);
    const int wr = (wid >> 2) * 16;        // 0 / 16
    const int wc = (wid & 3) * 16;         // 0 / 16 / 32 / 48
    uint32_t aAddr = smem_base + OFF_A +
        (uint32_t)(((wr + (lid & 15)) * AST + ((lid & 16) ? 8 : 0)) * 2);
    uint32_t bAddr = smem_base + OFF_B +
        (uint32_t)(((wc + (lid & 7) + ((lid & 16) ? 8 : 0)) * BST + ((lid & 8) ? 8 : 0)) * 2);

    int prevClass = 0;
    for (int c = 0; c < ncls; c++) {
        const int t   = cls[c];
        const int len = clen[c];
        const int off = coff[c];

        // class transition: rewrite A' rows with bi>0 for class t
        if (t > 0 && t != prevClass) {
            int v = g + 1;
            int cnt = rcnt[v - 1];
            if (cnt > 0) {
                int cc = 4 * (v - 1) + t;
                const float* Wc = g_W + (size_t)(cc * HNUM + h) * DDIM * DDIM + n;
                unsigned long long wp[32];
#pragma unroll
                for (int m2 = 0; m2 < 32; m2++)
                    wp[m2] = pack2(Wc[(2 * m2) * DDIM], Wc[(2 * m2 + 1) * DDIM]);
                int r = 0;
                for (; r + 1 < cnt; r += 2) {
                    urow(Qs, Ab, wp, rlist[(v - 1) * 32 + r], n);
                    urow(Qs, Ab, wp, rlist[(v - 1) * 32 + r + 1], n);
                }
                if (r < cnt) urow(Qs, Ab, wp, rlist[(v - 1) * 32 + r], n);
            }
            prevClass = t;
        }

        // copy chunk c K hi/lo into B' (chunk 0 done in prologue)
        if (c > 0) {
            uint4 h0, h1, l0, l1;
            if (j2 < len) {
                int jp = jperm[off + j2];
                const uint4* sh = (const uint4*)(khbase + (size_t)jp * DDIM + qq * 16);
                const uint4* sl = (const uint4*)(klbase + (size_t)jp * DDIM + qq * 16);
                h0 = sh[0]; h1 = sh[1]; l0 = sl[0]; l1 = sl[1];
            } else {
                h0 = h1 = l0 = l1 = make_uint4(0, 0, 0, 0);
            }
            uint32_t byt = (uint32_t)(j2 * BST + qq * 16) * 2;
            *(uint4*)(Bb + byt)       = h0;
            *(uint4*)(Bb + byt + 16)  = h1;
            *(uint4*)(Bb + byt + 128) = l0;
            *(uint4*)(Bb + byt + 144) = l1;
        }
        __syncthreads();   // A' + B' visible

        // ---- HMMA: 3 terms x 4 k-steps, warp tile 16x16 ----
        float d[2][4];
#pragma unroll
        for (int n8 = 0; n8 < 2; n8++)
#pragma unroll
            for (int e = 0; e < 4; e++) d[n8][e] = 0.f;

#pragma unroll
        for (int s = 0; s < 3; s++) {
            const uint32_t aOff = (s == 2) ? 128u : 0u;   // UL slice
            const uint32_t bOff = (s == 1) ? 128u : 0u;   // KL slice
#pragma unroll
            for (int ks = 0; ks < 4; ks++) {
                uint32_t a0[4], b0[4];
                LDSM4(a0, aAddr + aOff + ks * 32);
                LDSM4(b0, bAddr + bOff + ks * 32);
                MMA16816(d[0], a0, b0[0], b0[1]);
                MMA16816(d[1], a0, b0[2], b0[3]);
            }
        }

        // ---- scatter fragments into OUT smem (bank-cheap) ----
        {
            int row0 = wr + (lid >> 2);
            int p0   = wc + (lid & 3) * 2;
#pragma unroll
            for (int n8 = 0; n8 < 2; n8++) {
                int p = p0 + n8 * 8;
                if (p < len) {
                    int jp = jperm[off + p];
                    OUT[row0 * OSTR + jp]       = d[n8][0];
                    OUT[(row0 + 8) * OSTR + jp] = d[n8][2];
                }
                if (p + 1 < len) {
                    int jp = jperm[off + p + 1];
                    OUT[row0 * OSTR + jp]       = d[n8][1];
                    OUT[(row0 + 8) * OSTR + jp] = d[n8][3];
                }
            }
        }
        __syncthreads();   // B'/A' reads done before next chunk overwrites
    }

    // ---- coalesced flush: OUT smem -> gmem (ALL 32*128 float4s) ----
    float* outbase = out + ((size_t)bh * SLEN + i0) * SLEN;
    for (int x = tid; x < TI * (SLEN / 4); x += 256) {
        int row = x >> 7;          // 0..31
        int f4  = x & 127;         // float4 index within row
        ((float4*)(outbase + (size_t)row * SLEN))[f4] =
            *(const float4*)(OUT + row * OSTR + f4 * 4);
    }
}

// ---------------- launch ----------------
extern "C" void kernel_launch(void* const* d_in, const int* in_sizes, int n_in,
                              void* d_out, int out_size) {
    const float* q      = (const float*)d_in[0];
    const float* kk     = (const float*)d_in[1];
    const int*   bseq   = (const int*)  d_in[2];
    const float* W1     = (const float*)d_in[3];
    const float* alpha1 = (const float*)d_in[4];
    float* out = (float*)d_out;

    cudaFuncSetAttribute(mb_scores_kernel,
                         cudaFuncAttributeMaxDynamicSharedMemorySize, SMEM_BYTES);

    dim3 g1(CNUM, HNUM);
    wmix_kernel<<<g1, 256>>>(W1, alpha1);

    int nf4 = BNUM * HNUM * SLEN * DDIM / 4;   // float4 count
    ksplit_kernel<<<nf4 / 256, 256>>>(kk);

    dim3 g2(SLEN / TI, HNUM, BNUM);   // (16, 8, 8) = 1024 blocks
    mb_scores_kernel<<<g2, 256, SMEM_BYTES>>>(q, bseq, out);
}

// round 15
// speedup vs baseline: 1.6467x; 1.0345x over previous
#include <cuda_runtime.h>
#include <cuda_bf16.h>
#include <stdint.h>

#define NMB  4
#define CNUM 17
#define HNUM 8
#define BNUM 8
#define SLEN 512
#define DDIM 64
#define TI   32
#define JT   64
#define MAXCH 16
#define AST  136      // A' row stride (bf16)
#define BST  136      // B' row stride (bf16)
#define OSTR 516      // OUT smem row stride (floats)

// Premixed W1_: [C][h][m][n]  (n-major: lane-coalesced reads)
__device__ float g_W[CNUM * HNUM * DDIM * DDIM];

// ---- packed f32x2 helpers (phase A) ----
union F4U   { float4 f4; unsigned long long u[2]; };
union U64F2 { unsigned long long u; float2 f; };
__device__ __forceinline__ void ffma2(unsigned long long& d,
                                      unsigned long long a,
                                      unsigned long long b) {
    asm("fma.rn.f32x2 %0, %1, %2, %0;" : "+l"(d) : "l"(a), "l"(b));
}
__device__ __forceinline__ unsigned long long pack2(float x, float y) {
    unsigned long long r;
    asm("mov.b64 %0, {%1, %2};" : "=l"(r) : "f"(x), "f"(y));
    return r;
}
__device__ __forceinline__ float hadd2(unsigned long long a) {
    U64F2 x; x.u = a; return x.f.x + x.f.y;
}

// ---- HMMA helpers ----
#define LDSM4(r, a) \
    asm volatile("ldmatrix.sync.aligned.m8n8.x4.shared.b16 {%0,%1,%2,%3}, [%4];" \
        : "=r"((r)[0]), "=r"((r)[1]), "=r"((r)[2]), "=r"((r)[3]) : "r"(a))

#define MMA16816(d, a, b0v, b1v) \
    asm volatile("mma.sync.aligned.m16n8k16.row.col.f32.bf16.bf16.f32 " \
        "{%0,%1,%2,%3}, {%4,%5,%6,%7}, {%8,%9}, {%0,%1,%2,%3};" \
        : "+f"((d)[0]), "+f"((d)[1]), "+f"((d)[2]), "+f"((d)[3]) \
        : "r"((a)[0]), "r"((a)[1]), "r"((a)[2]), "r"((a)[3]), "r"(b0v), "r"(b1v))

// ---------------- Kernel 1: premix W (one thread per float2) ----------------
__global__ void wmix_kernel(const float* __restrict__ W1,
                            const float* __restrict__ alpha1) {
    int idx = blockIdx.x * 256 + threadIdx.x;       // float2 index
    if (idx >= CNUM * HNUM * DDIM * DDIM / 2) return;
    int ch = idx / 2048;                             // (c,h) block: 2048 float2 each
    int p  = idx - ch * 2048;
    int c = ch >> 3, h = ch & 7;

    float a[NMB];
#pragma unroll
    for (int B = 0; B < NMB; B++) a[B] = alpha1[(c * NMB + B) * HNUM + h];
    float mx = fmaxf(fmaxf(a[0], a[1]), fmaxf(a[2], a[3]));
    float w[NMB], s = 0.f;
#pragma unroll
    for (int B = 0; B < NMB; B++) { w[B] = __expf(a[B] - mx); s += w[B]; }
    float inv = 1.f / s;

    const float2* src = (const float2*)(W1 + h * DDIM * DDIM) + p;
    float2 acc = make_float2(0.f, 0.f);
#pragma unroll
    for (int B = 0; B < NMB; B++) {
        float2 v = src[B * HNUM * DDIM * DDIM / 2];
        acc.x += w[B] * v.x;
        acc.y += w[B] * v.y;
    }
    acc.x *= inv; acc.y *= inv;
    ((float2*)(g_W + (size_t)ch * DDIM * DDIM))[p] = acc;
}

// ---------------- shared layout (bytes) ----------------
#define OFF_Q    0                          // 32*64*4   = 8192
#define OFF_A    8192                       // 32*136*2  = 8704
#define OFF_B    (8192 + 8704)              // 64*136*2  = 17408
#define OFF_OUT  (OFF_B + 17408)            // 32*516*4  = 66048
#define OFF_INT  (OFF_OUT + 66048)
#define NINTS (512 + 512 + 128 + 8 + 8 + 8 + 8 + MAXCH * 3 + 4)
#define SMEM_BYTES (OFF_INT + NINTS * 4)

// phase-A row: U fp32 -> bf16 hi/lo into A' slices [UH | UL]
__device__ __forceinline__ void urow(const float* Qs, unsigned char* Ab,
                                     const unsigned long long* wp, int i, int n) {
    const F4U* qa = (const F4U*)(Qs + i * DDIM);
    unsigned long long a0 = 0, a1 = 0;
#pragma unroll
    for (int mb = 0; mb < 16; mb++) {
        F4U v = qa[mb];
        ffma2(a0, v.u[0], wp[2 * mb]);
        ffma2(a1, v.u[1], wp[2 * mb + 1]);
    }
    float u = hadd2(a0) + hadd2(a1);
    __nv_bfloat16 hi = __float2bfloat16(u);
    __nv_bfloat16 lo = __float2bfloat16(u - __bfloat162float(hi));
    uint32_t o = (uint32_t)(i * AST + n) * 2;
    *(__nv_bfloat16*)(Ab + o)       = hi;
    *(__nv_bfloat16*)(Ab + o + 128) = lo;
}

__device__ __forceinline__ void cvt4(float4 v, uint32_t& hw0, uint32_t& hw1,
                                     uint32_t& lw0, uint32_t& lw1) {
    __nv_bfloat162 h0 = __floats2bfloat162_rn(v.x, v.y);
    __nv_bfloat162 h1 = __floats2bfloat162_rn(v.z, v.w);
    float lx = v.x - __bfloat162float(h0.x);
    float ly = v.y - __bfloat162float(h0.y);
    float lz = v.z - __bfloat162float(h1.x);
    float lw = v.w - __bfloat162float(h1.y);
    __nv_bfloat162 l0 = __floats2bfloat162_rn(lx, ly);
    __nv_bfloat162 l1 = __floats2bfloat162_rn(lz, lw);
    hw0 = *(uint32_t*)&h0; hw1 = *(uint32_t*)&h1;
    lw0 = *(uint32_t*)&l0; lw1 = *(uint32_t*)&l1;
}

// copy one K chunk row-quarter: fp32 LDG -> bf16 hi/lo -> STS (completes pre-barrier)
__device__ __forceinline__ void bcopy(unsigned char* Bb, const float* kbase,
                                      const int* jperm, int off, int len,
                                      int j2, int qq) {
    uint32_t hw[4], lw[4];
    if (j2 < len) {
        int jp = jperm[off + j2];
        const float4* src = (const float4*)(kbase + (size_t)jp * DDIM + qq * 16);
        float4 v0 = src[0], v1 = src[1], v2 = src[2], v3 = src[3];
        cvt4(v0, hw[0], hw[1], lw[0], lw[1]);
        cvt4(v1, hw[2], hw[3], lw[2], lw[3]);
        uint32_t byt = (uint32_t)(j2 * BST + qq * 16) * 2;
        *(uint4*)(Bb + byt)       = make_uint4(hw[0], hw[1], hw[2], hw[3]);
        *(uint4*)(Bb + byt + 128) = make_uint4(lw[0], lw[1], lw[2], lw[3]);
        cvt4(v2, hw[0], hw[1], lw[0], lw[1]);
        cvt4(v3, hw[2], hw[3], lw[2], lw[3]);
        *(uint4*)(Bb + byt + 16)  = make_uint4(hw[0], hw[1], hw[2], hw[3]);
        *(uint4*)(Bb + byt + 144) = make_uint4(lw[0], lw[1], lw[2], lw[3]);
    } else {
        uint32_t byt = (uint32_t)(j2 * BST + qq * 16) * 2;
        uint4 z = make_uint4(0, 0, 0, 0);
        *(uint4*)(Bb + byt)       = z;
        *(uint4*)(Bb + byt + 16)  = z;
        *(uint4*)(Bb + byt + 128) = z;
        *(uint4*)(Bb + byt + 144) = z;
    }
}

__global__ __launch_bounds__(256, 2)
void mb_scores_kernel(const float* __restrict__ q,
                      const float* __restrict__ k,
                      const int*   __restrict__ bseq,
                      float* __restrict__ out) {
    extern __shared__ unsigned char smraw[];
    float* Qs = (float*)(smraw + OFF_Q);
    unsigned char* Ab = smraw + OFF_A;
    unsigned char* Bb = smraw + OFF_B;
    float* OUT = (float*)(smraw + OFF_OUT);
    int* bj_all = (int*)(smraw + OFF_INT);
    int* jperm  = bj_all + 512;
    int* rlist  = jperm + 512;
    int* jcnt   = rlist + 128;
    int* joff   = jcnt + 8;
    int* jpos   = joff + 8;
    int* rcnt   = jpos + 8;
    int* cls    = rcnt + 8;
    int* coff   = cls + MAXCH;
    int* clen   = coff + MAXCH;
    int* nchS   = clen + MAXCH;

    const int tid = threadIdx.x;
    const int wid = tid >> 5;
    const int lid = tid & 31;
    const int it  = blockIdx.x;
    const int h   = blockIdx.y;
    const int b   = blockIdx.z;
    const int i0  = it * TI;
    const int bh  = b * HNUM + h;

    const float* qbase = q + ((size_t)bh * SLEN + i0) * DDIM;
    const float* kbase = k + (size_t)bh * SLEN * DDIM;

    for (int t = tid; t < TI * DDIM / 4; t += 256)
        ((float4*)Qs)[t] = ((const float4*)qbase)[t];
    for (int t = tid; t < SLEN; t += 256) bj_all[t] = bseq[b * SLEN + t];
    if (tid < 8) { jcnt[tid] = 0; rcnt[tid] = 0; }
    __syncthreads();

    for (int t = tid; t < SLEN; t += 256) atomicAdd(&jcnt[bj_all[t]], 1);
    __syncthreads();
    if (tid == 0) {
        int s = 0;
        for (int t = 0; t < 5; t++) { joff[t] = s; jpos[t] = s; s += jcnt[t]; }
        int nc = 0;
        for (int t = 0; t < 5; t++) {
            int nt = jcnt[t], off = joff[t];
            for (int j0 = 0; j0 < nt; j0 += JT) {
                cls[nc] = t; coff[nc] = off + j0;
                clen[nc] = (nt - j0 < JT) ? (nt - j0) : JT;
                nc++;
            }
        }
        nchS[0] = nc;
    }
    __syncthreads();
    for (int t = tid; t < SLEN; t += 256) {
        int c = bj_all[t];
        int p = atomicAdd(&jpos[c], 1);
        jperm[p] = t;
    }
    for (int t = tid; t < TI; t += 256) {
        int c = bj_all[i0 + t];
        if (c > 0) { int p = atomicAdd(&rcnt[c - 1], 1); rlist[(c - 1) * 32 + p] = t; }
    }
    __syncthreads();

    const int ncls = nchS[0];
    const int n = tid & 63;
    const int g = tid >> 6;                  // 0..3
    const int j2 = tid >> 2, qq = tid & 3;   // copy mapping: row j2, quarter qq

    // ---- Phase A0: slot0 for all 32 rows (wp[32], proven) ----
    {
        const float* W0 = g_W + (size_t)h * DDIM * DDIM + n;   // c=0
        unsigned long long wp[32];
#pragma unroll
        for (int m2 = 0; m2 < 32; m2++)
            wp[m2] = pack2(W0[(2 * m2) * DDIM], W0[(2 * m2 + 1) * DDIM]);
        for (int r = 0; r < 8; r += 2) {
            urow(Qs, Ab, wp, g * 8 + r, n);
            urow(Qs, Ab, wp, g * 8 + r + 1, n);
        }
    }

    // ---- prologue: convert chunk 0 K into B' ----
    bcopy(Bb, kbase, jperm, coff[0], clen[0], j2, qq);
    __syncthreads();   // A0 + B'(chunk0) ready

    // ---- per-warp ldmatrix lane addressing (warp grid 2x4, tile 16x16) ----
    const uint32_t smem_base = (uint32_t)__cvta_generic_to_shared(smraw);
    const int wr = (wid >> 2) * 16;        // 0 / 16
    const int wc = (wid & 3) * 16;         // 0 / 16 / 32 / 48
    uint32_t aAddr = smem_base + OFF_A +
        (uint32_t)(((wr + (lid & 15)) * AST + ((lid & 16) ? 8 : 0)) * 2);
    uint32_t bAddr = smem_base + OFF_B +
        (uint32_t)(((wc + (lid & 7) + ((lid & 16) ? 8 : 0)) * BST + ((lid & 8) ? 8 : 0)) * 2);

    int prevClass = 0;
    for (int c = 0; c < ncls; c++) {
        const int t   = cls[c];
        const int len = clen[c];
        const int off = coff[c];

        // class transition: rewrite A' rows with bi>0 for class t
        if (t > 0 && t != prevClass) {
            int v = g + 1;
            int cnt = rcnt[v - 1];
            if (cnt > 0) {
                int cc = 4 * (v - 1) + t;
                const float* Wc = g_W + (size_t)(cc * HNUM + h) * DDIM * DDIM + n;
                unsigned long long wp[32];
#pragma unroll
                for (int m2 = 0; m2 < 32; m2++)
                    wp[m2] = pack2(Wc[(2 * m2) * DDIM], Wc[(2 * m2 + 1) * DDIM]);
                int r = 0;
                for (; r + 1 < cnt; r += 2) {
                    urow(Qs, Ab, wp, rlist[(v - 1) * 32 + r], n);
                    urow(Qs, Ab, wp, rlist[(v - 1) * 32 + r + 1], n);
                }
                if (r < cnt) urow(Qs, Ab, wp, rlist[(v - 1) * 32 + r], n);
            }
            prevClass = t;
        }

        // convert chunk c K into B' (chunk 0 done in prologue)
        if (c > 0) bcopy(Bb, kbase, jperm, off, len, j2, qq);
        __syncthreads();   // A' + B' visible

        // ---- HMMA: 3 terms x 4 k-steps, warp tile 16x16 ----
        float d[2][4];
#pragma unroll
        for (int n8 = 0; n8 < 2; n8++)
#pragma unroll
            for (int e = 0; e < 4; e++) d[n8][e] = 0.f;

#pragma unroll
        for (int s = 0; s < 3; s++) {
            const uint32_t aOff = (s == 2) ? 128u : 0u;   // UL slice
            const uint32_t bOff = (s == 1) ? 128u : 0u;   // KL slice
#pragma unroll
            for (int ks = 0; ks < 4; ks++) {
                uint32_t a0[4], b0[4];
                LDSM4(a0, aAddr + aOff + ks * 32);
                LDSM4(b0, bAddr + bOff + ks * 32);
                MMA16816(d[0], a0, b0[0], b0[1]);
                MMA16816(d[1], a0, b0[2], b0[3]);
            }
        }

        // ---- scatter fragments into OUT smem (bank-cheap) ----
        {
            int row0 = wr + (lid >> 2);
            int p0   = wc + (lid & 3) * 2;
#pragma unroll
            for (int n8 = 0; n8 < 2; n8++) {
                int p = p0 + n8 * 8;
                if (p < len) {
                    int jp = jperm[off + p];
                    OUT[row0 * OSTR + jp]       = d[n8][0];
                    OUT[(row0 + 8) * OSTR + jp] = d[n8][2];
                }
                if (p + 1 < len) {
                    int jp = jperm[off + p + 1];
                    OUT[row0 * OSTR + jp]       = d[n8][1];
                    OUT[(row0 + 8) * OSTR + jp] = d[n8][3];
                }
            }
        }
        __syncthreads();   // B'/A' reads done before next chunk overwrites
    }

    // ---- coalesced flush: OUT smem -> gmem (ALL 32*128 float4s) ----
    float* outbase = out + ((size_t)bh * SLEN + i0) * SLEN;
    for (int x = tid; x < TI * (SLEN / 4); x += 256) {
        int row = x >> 7;          // 0..31
        int f4  = x & 127;         // float4 index within row
        ((float4*)(outbase + (size_t)row * SLEN))[f4] =
            *(const float4*)(OUT + row * OSTR + f4 * 4);
    }
}

// ---------------- launch ----------------
extern "C" void kernel_launch(void* const* d_in, const int* in_sizes, int n_in,
                              void* d_out, int out_size) {
    const float* q      = (const float*)d_in[0];
    const float* kk     = (const float*)d_in[1];
    const int*   bseq   = (const int*)  d_in[2];
    const float* W1     = (const float*)d_in[3];
    const float* alpha1 = (const float*)d_in[4];
    float* out = (float*)d_out;

    cudaFuncSetAttribute(mb_scores_kernel,
                         cudaFuncAttributeMaxDynamicSharedMemorySize, SMEM_BYTES);

    int nwmix = (CNUM * HNUM * DDIM * DDIM / 2 + 255) / 256;   // 1088 blocks
    wmix_kernel<<<nwmix, 256>>>(W1, alpha1);

    dim3 g2(SLEN / TI, HNUM, BNUM);   // (16, 8, 8) = 1024 blocks
    mb_scores_kernel<<<g2, 256, SMEM_BYTES>>>(q, kk, bseq, out);
}

// round 16
// speedup vs baseline: 1.6668x; 1.0122x over previous
#include <cuda_runtime.h>
#include <cuda_bf16.h>
#include <stdint.h>

#define NMB  4
#define CNUM 17
#define HNUM 8
#define BNUM 8
#define SLEN 512
#define DDIM 64
#define TI   32
#define JT   64
#define MAXCH 16
#define AST  136      // A' row stride (bf16)
#define BST  136      // B' row stride (bf16)
#define OSTR 516      // OUT smem row stride (floats)

// Premixed W1_: [C][h][m][n]  (n-major: lane-coalesced reads)
__device__ float g_W[CNUM * HNUM * DDIM * DDIM];
// Pre-split K: bf16 hi/lo, [b,h,S,d]
__device__ __nv_bfloat16 g_Khi[BNUM * HNUM * SLEN * DDIM];
__device__ __nv_bfloat16 g_Klo[BNUM * HNUM * SLEN * DDIM];

// ---- packed f32x2 helpers (phase A) ----
union F4U   { float4 f4; unsigned long long u[2]; };
union U64F2 { unsigned long long u; float2 f; };
__device__ __forceinline__ void ffma2(unsigned long long& d,
                                      unsigned long long a,
                                      unsigned long long b) {
    asm("fma.rn.f32x2 %0, %1, %2, %0;" : "+l"(d) : "l"(a), "l"(b));
}
__device__ __forceinline__ unsigned long long pack2(float x, float y) {
    unsigned long long r;
    asm("mov.b64 %0, {%1, %2};" : "=l"(r) : "f"(x), "f"(y));
    return r;
}
__device__ __forceinline__ float hadd2(unsigned long long a) {
    U64F2 x; x.u = a; return x.f.x + x.f.y;
}

// ---- HMMA helpers ----
#define LDSM4(r, a) \
    asm volatile("ldmatrix.sync.aligned.m8n8.x4.shared.b16 {%0,%1,%2,%3}, [%4];" \
        : "=r"((r)[0]), "=r"((r)[1]), "=r"((r)[2]), "=r"((r)[3]) : "r"(a))

#define MMA16816(d, a, b0v, b1v) \
    asm volatile("mma.sync.aligned.m16n8k16.row.col.f32.bf16.bf16.f32 " \
        "{%0,%1,%2,%3}, {%4,%5,%6,%7}, {%8,%9}, {%0,%1,%2,%3};" \
        : "+f"((d)[0]), "+f"((d)[1]), "+f"((d)[2]), "+f"((d)[3]) \
        : "r"((a)[0]), "r"((a)[1]), "r"((a)[2]), "r"((a)[3]), "r"(b0v), "r"(b1v))

// ---------------- Kernel 1: premix W (one thread per float2) ----------------
__global__ void wmix_kernel(const float* __restrict__ W1,
                            const float* __restrict__ alpha1) {
    int idx = blockIdx.x * 256 + threadIdx.x;       // float2 index
    if (idx >= CNUM * HNUM * DDIM * DDIM / 2) return;
    int ch = idx / 2048;                             // (c,h) block: 2048 float2 each
    int p  = idx - ch * 2048;
    int c = ch >> 3, h = ch & 7;

    float a[NMB];
#pragma unroll
    for (int B = 0; B < NMB; B++) a[B] = alpha1[(c * NMB + B) * HNUM + h];
    float mx = fmaxf(fmaxf(a[0], a[1]), fmaxf(a[2], a[3]));
    float w[NMB], s = 0.f;
#pragma unroll
    for (int B = 0; B < NMB; B++) { w[B] = __expf(a[B] - mx); s += w[B]; }
    float inv = 1.f / s;

    const float2* src = (const float2*)(W1 + h * DDIM * DDIM) + p;
    float2 acc = make_float2(0.f, 0.f);
#pragma unroll
    for (int B = 0; B < NMB; B++) {
        float2 v = src[B * HNUM * DDIM * DDIM / 2];
        acc.x += w[B] * v.x;
        acc.y += w[B] * v.y;
    }
    acc.x *= inv; acc.y *= inv;
    ((float2*)(g_W + (size_t)ch * DDIM * DDIM))[p] = acc;
}

// ---------------- Kernel 2: pre-split K into bf16 hi/lo ----------------
__global__ void ksplit_kernel(const float* __restrict__ k) {
    int idx = blockIdx.x * 256 + threadIdx.x;   // float4 index
    float4 v = ((const float4*)k)[idx];
    __nv_bfloat162 h0 = __floats2bfloat162_rn(v.x, v.y);
    __nv_bfloat162 h1 = __floats2bfloat162_rn(v.z, v.w);
    __nv_bfloat162 l0 = __floats2bfloat162_rn(v.x - __bfloat162float(h0.x),
                                              v.y - __bfloat162float(h0.y));
    __nv_bfloat162 l1 = __floats2bfloat162_rn(v.z - __bfloat162float(h1.x),
                                              v.w - __bfloat162float(h1.y));
    uint2 hw, lw;
    hw.x = *(uint32_t*)&h0; hw.y = *(uint32_t*)&h1;
    lw.x = *(uint32_t*)&l0; lw.y = *(uint32_t*)&l1;
    ((uint2*)g_Khi)[idx] = hw;
    ((uint2*)g_Klo)[idx] = lw;
}

// ---------------- shared layout (bytes) ----------------
#define OFF_Q    0                          // 32*64*4   = 8192
#define OFF_A    8192                       // 32*136*2  = 8704
#define OFF_B    (8192 + 8704)              // 64*136*2  = 17408
#define OFF_OUT  (OFF_B + 17408)            // 32*516*4  = 66048
#define OFF_INT  (OFF_OUT + 66048)
#define NINTS (512 + 512 + 128 + 8 + 8 + 8 + 8 + MAXCH * 3 + 4)
#define SMEM_BYTES (OFF_INT + NINTS * 4)

// phase-A row: U fp32 -> bf16 hi/lo into A' slices [UH | UL]
__device__ __forceinline__ void urow(const float* Qs, unsigned char* Ab,
                                     const unsigned long long* wp, int i, int n) {
    const F4U* qa = (const F4U*)(Qs + i * DDIM);
    unsigned long long a0 = 0, a1 = 0;
#pragma unroll
    for (int mb = 0; mb < 16; mb++) {
        F4U v = qa[mb];
        ffma2(a0, v.u[0], wp[2 * mb]);
        ffma2(a1, v.u[1], wp[2 * mb + 1]);
    }
    float u = hadd2(a0) + hadd2(a1);
    __nv_bfloat16 hi = __float2bfloat16(u);
    __nv_bfloat16 lo = __float2bfloat16(u - __bfloat162float(hi));
    uint32_t o = (uint32_t)(i * AST + n) * 2;
    *(__nv_bfloat16*)(Ab + o)       = hi;
    *(__nv_bfloat16*)(Ab + o + 128) = lo;
}

__global__ __launch_bounds__(256, 2)
void mb_scores_kernel(const float* __restrict__ q,
                      const int*   __restrict__ bseq,
                      float* __restrict__ out) {
    extern __shared__ unsigned char smraw[];
    float* Qs = (float*)(smraw + OFF_Q);
    unsigned char* Ab = smraw + OFF_A;
    unsigned char* Bb = smraw + OFF_B;
    float* OUT = (float*)(smraw + OFF_OUT);
    int* bj_all = (int*)(smraw + OFF_INT);
    int* jperm  = bj_all + 512;
    int* rlist  = jperm + 512;
    int* jcnt   = rlist + 128;
    int* joff   = jcnt + 8;
    int* jpos   = joff + 8;
    int* rcnt   = jpos + 8;
    int* cls    = rcnt + 8;
    int* coff   = cls + MAXCH;
    int* clen   = coff + MAXCH;
    int* nchS   = clen + MAXCH;

    const int tid = threadIdx.x;
    const int wid = tid >> 5;
    const int lid = tid & 31;
    const int it  = blockIdx.x;
    const int h   = blockIdx.y;
    const int b   = blockIdx.z;
    const int i0  = it * TI;
    const int bh  = b * HNUM + h;

    const float* qbase = q + ((size_t)bh * SLEN + i0) * DDIM;
    const __nv_bfloat16* khbase = g_Khi + (size_t)bh * SLEN * DDIM;
    const __nv_bfloat16* klbase = g_Klo + (size_t)bh * SLEN * DDIM;

    for (int t = tid; t < TI * DDIM / 4; t += 256)
        ((float4*)Qs)[t] = ((const float4*)qbase)[t];
    for (int t = tid; t < SLEN; t += 256) bj_all[t] = bseq[b * SLEN + t];
    if (tid < 8) { jcnt[tid] = 0; rcnt[tid] = 0; }
    __syncthreads();

    for (int t = tid; t < SLEN; t += 256) atomicAdd(&jcnt[bj_all[t]], 1);
    __syncthreads();
    if (tid == 0) {
        int s = 0;
        for (int t = 0; t < 5; t++) { joff[t] = s; jpos[t] = s; s += jcnt[t]; }
        int nc = 0;
        for (int t = 0; t < 5; t++) {
            int nt = jcnt[t], off = joff[t];
            for (int j0 = 0; j0 < nt; j0 += JT) {
                cls[nc] = t; coff[nc] = off + j0;
                clen[nc] = (nt - j0 < JT) ? (nt - j0) : JT;
                nc++;
            }
        }
        nchS[0] = nc;
    }
    __syncthreads();
    for (int t = tid; t < SLEN; t += 256) {
        int c = bj_all[t];
        int p = atomicAdd(&jpos[c], 1);
        jperm[p] = t;
    }
    for (int t = tid; t < TI; t += 256) {
        int c = bj_all[i0 + t];
        if (c > 0) { int p = atomicAdd(&rcnt[c - 1], 1); rlist[(c - 1) * 32 + p] = t; }
    }
    __syncthreads();

    const int ncls = nchS[0];
    const int n = tid & 63;
    const int g = tid >> 6;              // 0..3
    const int j2 = tid >> 2, qq = tid & 3;   // copy mapping: row j2, quarter qq

    // ---- Phase A0: slot0 for all 32 rows (wp[32], proven) ----
    {
        const float* W0 = g_W + (size_t)h * DDIM * DDIM + n;   // c=0
        unsigned long long wp[32];
#pragma unroll
        for (int m2 = 0; m2 < 32; m2++)
            wp[m2] = pack2(W0[(2 * m2) * DDIM], W0[(2 * m2 + 1) * DDIM]);
        for (int r = 0; r < 8; r += 2) {
            urow(Qs, Ab, wp, g * 8 + r, n);
            urow(Qs, Ab, wp, g * 8 + r + 1, n);
        }
    }

    // ---- prologue: copy chunk 0 K hi/lo into B' ----
    {
        int len0 = clen[0], off0 = coff[0];
        uint4 h0, h1, l0, l1;
        if (j2 < len0) {
            int jp = jperm[off0 + j2];
            const uint4* sh = (const uint4*)(khbase + (size_t)jp * DDIM + qq * 16);
            const uint4* sl = (const uint4*)(klbase + (size_t)jp * DDIM + qq * 16);
            h0 = sh[0]; h1 = sh[1]; l0 = sl[0]; l1 = sl[1];
        } else {
            h0 = h1 = l0 = l1 = make_uint4(0, 0, 0, 0);
        }
        uint32_t byt = (uint32_t)(j2 * BST + qq * 16) * 2;
        *(uint4*)(Bb + byt)        = h0;
        *(uint4*)(Bb + byt + 16)   = h1;
        *(uint4*)(Bb + byt + 128)  = l0;   // lo slice: +64 elems = +128B
        *(uint4*)(Bb + byt + 144)  = l1;
    }
    __syncthreads();   // A0 + B'(chunk0) ready

    // ---- per-warp ldmatrix lane addressing (warp grid 2x4, tile 16x16) ----
    const uint32_t smem_base = (uint32_t)__cvta_generic_to_shared(smraw);
    const int wr = (wid >> 2) * 16;        // 0 / 16
    const int wc = (wid & 3) * 16;         // 0 / 16 / 32 / 48
    uint32_t aAddr = smem_base + OFF_A +
        (uint32_t)(((wr + (lid & 15)) * AST + ((lid & 16) ? 8 : 0)) * 2);
    uint32_t bAddr = smem_base + OFF_B +
        (uint32_t)(((wc + (lid & 7) + ((lid & 16) ? 8 : 0)) * BST + ((lid & 8) ? 8 : 0)) * 2);

    int prevClass = 0;
    for (int c = 0; c < ncls; c++) {
        const int t   = cls[c];
        const int len = clen[c];
        const int off = coff[c];

        // class transition: rewrite A' rows with bi>0 for class t
        if (t > 0 && t != prevClass) {
            int v = g + 1;
            int cnt = rcnt[v - 1];
            if (cnt > 0) {
                int cc = 4 * (v - 1) + t;
                const float* Wc = g_W + (size_t)(cc * HNUM + h) * DDIM * DDIM + n;
                unsigned long long wp[32];
#pragma unroll
                for (int m2 = 0; m2 < 32; m2++)
                    wp[m2] = pack2(Wc[(2 * m2) * DDIM], Wc[(2 * m2 + 1) * DDIM]);
                int r = 0;
                for (; r + 1 < cnt; r += 2) {
                    urow(Qs, Ab, wp, rlist[(v - 1) * 32 + r], n);
                    urow(Qs, Ab, wp, rlist[(v - 1) * 32 + r + 1], n);
                }
                if (r < cnt) urow(Qs, Ab, wp, rlist[(v - 1) * 32 + r], n);
            }
            prevClass = t;
        }

        // copy chunk c K hi/lo into B' (chunk 0 done in prologue)
        if (c > 0) {
            uint4 h0, h1, l0, l1;
            if (j2 < len) {
                int jp = jperm[off + j2];
                const uint4* sh = (const uint4*)(khbase + (size_t)jp * DDIM + qq * 16);
                const uint4* sl = (const uint4*)(klbase + (size_t)jp * DDIM + qq * 16);
                h0 = sh[0]; h1 = sh[1]; l0 = sl[0]; l1 = sl[1];
            } else {
                h0 = h1 = l0 = l1 = make_uint4(0, 0, 0, 0);
            }
            uint32_t byt = (uint32_t)(j2 * BST + qq * 16) * 2;
            *(uint4*)(Bb + byt)       = h0;
            *(uint4*)(Bb + byt + 16)  = h1;
            *(uint4*)(Bb + byt + 128) = l0;
            *(uint4*)(Bb + byt + 144) = l1;
        }
        __syncthreads();   // A' + B' visible

        // ---- HMMA: 3 terms x 4 k-steps, warp tile 16x16 ----
        float d[2][4];
#pragma unroll
        for (int n8 = 0; n8 < 2; n8++)
#pragma unroll
            for (int e = 0; e < 4; e++) d[n8][e] = 0.f;

#pragma unroll
        for (int s = 0; s < 3; s++) {
            const uint32_t aOff = (s == 2) ? 128u : 0u;   // UL slice
            const uint32_t bOff = (s == 1) ? 128u : 0u;   // KL slice
#pragma unroll
            for (int ks = 0; ks < 4; ks++) {
                uint32_t a0[4], b0[4];
                LDSM4(a0, aAddr + aOff + ks * 32);
                LDSM4(b0, bAddr + bOff + ks * 32);
                MMA16816(d[0], a0, b0[0], b0[1]);
                MMA16816(d[1], a0, b0[2], b0[3]);
            }
        }

        // ---- scatter fragments into OUT smem (bank-cheap) ----
        {
            int row0 = wr + (lid >> 2);
            int p0   = wc + (lid & 3) * 2;
#pragma unroll
            for (int n8 = 0; n8 < 2; n8++) {
                int p = p0 + n8 * 8;
                if (p < len) {
                    int jp = jperm[off + p];
                    OUT[row0 * OSTR + jp]       = d[n8][0];
                    OUT[(row0 + 8) * OSTR + jp] = d[n8][2];
                }
                if (p + 1 < len) {
                    int jp = jperm[off + p + 1];
                    OUT[row0 * OSTR + jp]       = d[n8][1];
                    OUT[(row0 + 8) * OSTR + jp] = d[n8][3];
                }
            }
        }
        __syncthreads();   // B'/A' reads done before next chunk overwrites
    }

    // ---- coalesced flush: OUT smem -> gmem (ALL 32*128 float4s) ----
    float* outbase = out + ((size_t)bh * SLEN + i0) * SLEN;
    for (int x = tid; x < TI * (SLEN / 4); x += 256) {
        int row = x >> 7;          // 0..31
        int f4  = x & 127;         // float4 index within row
        ((float4*)(outbase + (size_t)row * SLEN))[f4] =
            *(const float4*)(OUT + row * OSTR + f4 * 4);
    }
}

// ---------------- launch ----------------
extern "C" void kernel_launch(void* const* d_in, const int* in_sizes, int n_in,
                              void* d_out, int out_size) {
    const float* q      = (const float*)d_in[0];
    const float* kk     = (const float*)d_in[1];
    const int*   bseq   = (const int*)  d_in[2];
    const float* W1     = (const float*)d_in[3];
    const float* alpha1 = (const float*)d_in[4];
    float* out = (float*)d_out;

    cudaFuncSetAttribute(mb_scores_kernel,
                         cudaFuncAttributeMaxDynamicSharedMemorySize, SMEM_BYTES);

    int nwmix = (CNUM * HNUM * DDIM * DDIM / 2 + 255) / 256;   // 1088 blocks
    wmix_kernel<<<nwmix, 256>>>(W1, alpha1);

    int nf4 = BNUM * HNUM * SLEN * DDIM / 4;   // float4 count
    ksplit_kernel<<<nf4 / 256, 256>>>(kk);

    dim3 g2(SLEN / TI, HNUM, BNUM);   // (16, 8, 8) = 1024 blocks
    mb_scores_kernel<<<g2, 256, SMEM_BYTES>>>(q, bseq, out);
}

// round 17
// speedup vs baseline: 1.6953x; 1.0171x over previous
#include <cuda_runtime.h>
#include <cuda_bf16.h>
#include <stdint.h>

#define NMB  4
#define CNUM 17
#define HNUM 8
#define BNUM 8
#define SLEN 512
#define DDIM 64
#define TI   32
#define JT   64
#define MAXCH 16
#define AST  136      // A' row stride (bf16)
#define BST  136      // B' row stride (bf16)
#define OSTR 516      // OUT smem row stride (floats)

#define KSPLIT_BLOCKS (BNUM * HNUM * SLEN * DDIM / 4 / 256)          // 512
#define WMIX_ITEMS    (CNUM * HNUM * DDIM * DDIM / 2)                 // 278528
#define WMIX_BLOCKS   ((WMIX_ITEMS + 255) / 256)                      // 1088

// Premixed W1_: [C][h][m][n]  (n-major: lane-coalesced reads)
__device__ float g_W[CNUM * HNUM * DDIM * DDIM];
// Pre-split K: bf16 hi/lo, [b,h,S,d]
__device__ __nv_bfloat16 g_Khi[BNUM * HNUM * SLEN * DDIM];
__device__ __nv_bfloat16 g_Klo[BNUM * HNUM * SLEN * DDIM];

// ---- packed f32x2 helpers (phase A) ----
union F4U   { float4 f4; unsigned long long u[2]; };
union U64F2 { unsigned long long u; float2 f; };
__device__ __forceinline__ void ffma2(unsigned long long& d,
                                      unsigned long long a,
                                      unsigned long long b) {
    asm("fma.rn.f32x2 %0, %1, %2, %0;" : "+l"(d) : "l"(a), "l"(b));
}
__device__ __forceinline__ unsigned long long pack2(float x, float y) {
    unsigned long long r;
    asm("mov.b64 %0, {%1, %2};" : "=l"(r) : "f"(x), "f"(y));
    return r;
}
__device__ __forceinline__ float hadd2(unsigned long long a) {
    U64F2 x; x.u = a; return x.f.x + x.f.y;
}

// ---- HMMA helpers ----
#define LDSM4(r, a) \
    asm volatile("ldmatrix.sync.aligned.m8n8.x4.shared.b16 {%0,%1,%2,%3}, [%4];" \
        : "=r"((r)[0]), "=r"((r)[1]), "=r"((r)[2]), "=r"((r)[3]) : "r"(a))

#define MMA16816(d, a, b0v, b1v) \
    asm volatile("mma.sync.aligned.m16n8k16.row.col.f32.bf16.bf16.f32 " \
        "{%0,%1,%2,%3}, {%4,%5,%6,%7}, {%8,%9}, {%0,%1,%2,%3};" \
        : "+f"((d)[0]), "+f"((d)[1]), "+f"((d)[2]), "+f"((d)[3]) \
        : "r"((a)[0]), "r"((a)[1]), "r"((a)[2]), "r"((a)[3]), "r"(b0v), "r"(b1v))

// ---------------- Fused prep: ksplit (blocks [0,512)) + wmix (blocks [512,1600)) ----
__global__ void prep_kernel(const float* __restrict__ W1,
                            const float* __restrict__ alpha1,
                            const float* __restrict__ k) {
    if (blockIdx.x < KSPLIT_BLOCKS) {
        // ---- ksplit: pre-split K into bf16 hi/lo ----
        int idx = blockIdx.x * 256 + threadIdx.x;   // float4 index
        float4 v = ((const float4*)k)[idx];
        __nv_bfloat162 h0 = __floats2bfloat162_rn(v.x, v.y);
        __nv_bfloat162 h1 = __floats2bfloat162_rn(v.z, v.w);
        __nv_bfloat162 l0 = __floats2bfloat162_rn(v.x - __bfloat162float(h0.x),
                                                  v.y - __bfloat162float(h0.y));
        __nv_bfloat162 l1 = __floats2bfloat162_rn(v.z - __bfloat162float(h1.x),
                                                  v.w - __bfloat162float(h1.y));
        uint2 hw, lw;
        hw.x = *(uint32_t*)&h0; hw.y = *(uint32_t*)&h1;
        lw.x = *(uint32_t*)&l0; lw.y = *(uint32_t*)&l1;
        ((uint2*)g_Khi)[idx] = hw;
        ((uint2*)g_Klo)[idx] = lw;
    } else {
        // ---- wmix: one thread per float2 of g_W ----
        int idx = (blockIdx.x - KSPLIT_BLOCKS) * 256 + threadIdx.x;
        if (idx >= WMIX_ITEMS) return;
        int ch = idx / 2048;                         // (c,h) block: 2048 float2 each
        int p  = idx - ch * 2048;
        int c = ch >> 3, h = ch & 7;

        float a[NMB];
#pragma unroll
        for (int B = 0; B < NMB; B++) a[B] = alpha1[(c * NMB + B) * HNUM + h];
        float mx = fmaxf(fmaxf(a[0], a[1]), fmaxf(a[2], a[3]));
        float w[NMB], s = 0.f;
#pragma unroll
        for (int B = 0; B < NMB; B++) { w[B] = __expf(a[B] - mx); s += w[B]; }
        float inv = 1.f / s;

        const float2* src = (const float2*)(W1 + h * DDIM * DDIM) + p;
        float2 acc = make_float2(0.f, 0.f);
#pragma unroll
        for (int B = 0; B < NMB; B++) {
            float2 v = src[B * HNUM * DDIM * DDIM / 2];
            acc.x += w[B] * v.x;
            acc.y += w[B] * v.y;
        }
        acc.x *= inv; acc.y *= inv;
        ((float2*)(g_W + (size_t)ch * DDIM * DDIM))[p] = acc;
    }
}

// ---------------- shared layout (bytes) ----------------
#define OFF_Q    0                          // 32*64*4   = 8192
#define OFF_A    8192                       // 32*136*2  = 8704
#define OFF_B    (8192 + 8704)              // 64*136*2  = 17408
#define OFF_OUT  (OFF_B + 17408)            // 32*516*4  = 66048
#define OFF_INT  (OFF_OUT + 66048)
#define NINTS (512 + 512 + 128 + 8 + 8 + 8 + 8 + MAXCH * 3 + 4)
#define SMEM_BYTES (OFF_INT + NINTS * 4)

// phase-A row: U fp32 -> bf16 hi/lo into A' slices [UH | UL]
__device__ __forceinline__ void urow(const float* Qs, unsigned char* Ab,
                                     const unsigned long long* wp, int i, int n) {
    const F4U* qa = (const F4U*)(Qs + i * DDIM);
    unsigned long long a0 = 0, a1 = 0;
#pragma unroll
    for (int mb = 0; mb < 16; mb++) {
        F4U v = qa[mb];
        ffma2(a0, v.u[0], wp[2 * mb]);
        ffma2(a1, v.u[1], wp[2 * mb + 1]);
    }
    float u = hadd2(a0) + hadd2(a1);
    __nv_bfloat16 hi = __float2bfloat16(u);
    __nv_bfloat16 lo = __float2bfloat16(u - __bfloat162float(hi));
    uint32_t o = (uint32_t)(i * AST + n) * 2;
    *(__nv_bfloat16*)(Ab + o)       = hi;
    *(__nv_bfloat16*)(Ab + o + 128) = lo;
}

__global__ __launch_bounds__(256, 2)
void mb_scores_kernel(const float* __restrict__ q,
                      const int*   __restrict__ bseq,
                      float* __restrict__ out) {
    extern __shared__ unsigned char smraw[];
    float* Qs = (float*)(smraw + OFF_Q);
    unsigned char* Ab = smraw + OFF_A;
    unsigned char* Bb = smraw + OFF_B;
    float* OUT = (float*)(smraw + OFF_OUT);
    int* bj_all = (int*)(smraw + OFF_INT);
    int* jperm  = bj_all + 512;
    int* rlist  = jperm + 512;
    int* jcnt   = rlist + 128;
    int* joff   = jcnt + 8;
    int* jpos   = joff + 8;
    int* rcnt   = jpos + 8;
    int* cls    = rcnt + 8;
    int* coff   = cls + MAXCH;
    int* clen   = coff + MAXCH;
    int* nchS   = clen + MAXCH;

    const int tid = threadIdx.x;
    const int wid = tid >> 5;
    const int lid = tid & 31;
    const int it  = blockIdx.x;
    const int h   = blockIdx.y;
    const int b   = blockIdx.z;
    const int i0  = it * TI;
    const int bh  = b * HNUM + h;

    const float* qbase = q + ((size_t)bh * SLEN + i0) * DDIM;
    const __nv_bfloat16* khbase = g_Khi + (size_t)bh * SLEN * DDIM;
    const __nv_bfloat16* klbase = g_Klo + (size_t)bh * SLEN * DDIM;

    for (int t = tid; t < TI * DDIM / 4; t += 256)
        ((float4*)Qs)[t] = ((const float4*)qbase)[t];
    for (int t = tid; t < SLEN; t += 256) bj_all[t] = bseq[b * SLEN + t];
    if (tid < 8) { jcnt[tid] = 0; rcnt[tid] = 0; }
    __syncthreads();

    for (int t = tid; t < SLEN; t += 256) atomicAdd(&jcnt[bj_all[t]], 1);
    __syncthreads();
    if (tid == 0) {
        int s = 0;
        for (int t = 0; t < 5; t++) { joff[t] = s; jpos[t] = s; s += jcnt[t]; }
        int nc = 0;
        for (int t = 0; t < 5; t++) {
            int nt = jcnt[t], off = joff[t];
            for (int j0 = 0; j0 < nt; j0 += JT) {
                cls[nc] = t; coff[nc] = off + j0;
                clen[nc] = (nt - j0 < JT) ? (nt - j0) : JT;
                nc++;
            }
        }
        nchS[0] = nc;
    }
    __syncthreads();
    for (int t = tid; t < SLEN; t += 256) {
        int c = bj_all[t];
        int p = atomicAdd(&jpos[c], 1);
        jperm[p] = t;
    }
    for (int t = tid; t < TI; t += 256) {
        int c = bj_all[i0 + t];
        if (c > 0) { int p = atomicAdd(&rcnt[c - 1], 1); rlist[(c - 1) * 32 + p] = t; }
    }
    __syncthreads();

    const int ncls = nchS[0];
    const int n = tid & 63;
    const int g = tid >> 6;              // 0..3
    const int j2 = tid >> 2, qq = tid & 3;   // copy mapping: row j2, quarter qq

    // ---- Phase A0: slot0 for all 32 rows (wp[32], proven) ----
    {
        const float* W0 = g_W + (size_t)h * DDIM * DDIM + n;   // c=0
        unsigned long long wp[32];
#pragma unroll
        for (int m2 = 0; m2 < 32; m2++)
            wp[m2] = pack2(W0[(2 * m2) * DDIM], W0[(2 * m2 + 1) * DDIM]);
        for (int r = 0; r < 8; r += 2) {
            urow(Qs, Ab, wp, g * 8 + r, n);
            urow(Qs, Ab, wp, g * 8 + r + 1, n);
        }
    }

    // ---- prologue: copy chunk 0 K hi/lo into B' ----
    {
        int len0 = clen[0], off0 = coff[0];
        uint4 h0, h1, l0, l1;
        if (j2 < len0) {
            int jp = jperm[off0 + j2];
            const uint4* sh = (const uint4*)(khbase + (size_t)jp * DDIM + qq * 16);
            const uint4* sl = (const uint4*)(klbase + (size_t)jp * DDIM + qq * 16);
            h0 = sh[0]; h1 = sh[1]; l0 = sl[0]; l1 = sl[1];
        } else {
            h0 = h1 = l0 = l1 = make_uint4(0, 0, 0, 0);
        }
        uint32_t byt = (uint32_t)(j2 * BST + qq * 16) * 2;
        *(uint4*)(Bb + byt)        = h0;
        *(uint4*)(Bb + byt + 16)   = h1;
        *(uint4*)(Bb + byt + 128)  = l0;   // lo slice: +64 elems = +128B
        *(uint4*)(Bb + byt + 144)  = l1;
    }
    __syncthreads();   // A0 + B'(chunk0) ready

    // ---- per-warp ldmatrix lane addressing (warp grid 2x4, tile 16x16) ----
    const uint32_t smem_base = (uint32_t)__cvta_generic_to_shared(smraw);
    const int wr = (wid >> 2) * 16;        // 0 / 16
    const int wc = (wid & 3) * 16;         // 0 / 16 / 32 / 48
    uint32_t aAddr = smem_base + OFF_A +
        (uint32_t)(((wr + (lid & 15)) * AST + ((lid & 16) ? 8 : 0)) * 2);
    uint32_t bAddr = smem_base + OFF_B +
        (uint32_t)(((wc + (lid & 7) + ((lid & 16) ? 8 : 0)) * BST + ((lid & 8) ? 8 : 0)) * 2);

    int prevClass = 0;
    for (int c = 0; c < ncls; c++) {
        const int t   = cls[c];
        const int len = clen[c];
        const int off = coff[c];

        // class transition: rewrite A' rows with bi>0 for class t
        if (t > 0 && t != prevClass) {
            int v = g + 1;
            int cnt = rcnt[v - 1];
            if (cnt > 0) {
                int cc = 4 * (v - 1) + t;
                const float* Wc = g_W + (size_t)(cc * HNUM + h) * DDIM * DDIM + n;
                unsigned long long wp[32];
#pragma unroll
                for (int m2 = 0; m2 < 32; m2++)
                    wp[m2] = pack2(Wc[(2 * m2) * DDIM], Wc[(2 * m2 + 1) * DDIM]);
                int r = 0;
                for (; r + 1 < cnt; r += 2) {
                    urow(Qs, Ab, wp, rlist[(v - 1) * 32 + r], n);
                    urow(Qs, Ab, wp, rlist[(v - 1) * 32 + r + 1], n);
                }
                if (r < cnt) urow(Qs, Ab, wp, rlist[(v - 1) * 32 + r], n);
            }
            prevClass = t;
        }

        // copy chunk c K hi/lo into B' (chunk 0 done in prologue)
        if (c > 0) {
            uint4 h0, h1, l0, l1;
            if (j2 < len) {
                int jp = jperm[off + j2];
                const uint4* sh = (const uint4*)(khbase + (size_t)jp * DDIM + qq * 16);
                const uint4* sl = (const uint4*)(klbase + (size_t)jp * DDIM + qq * 16);
                h0 = sh[0]; h1 = sh[1]; l0 = sl[0]; l1 = sl[1];
            } else {
                h0 = h1 = l0 = l1 = make_uint4(0, 0, 0, 0);
            }
            uint32_t byt = (uint32_t)(j2 * BST + qq * 16) * 2;
            *(uint4*)(Bb + byt)       = h0;
            *(uint4*)(Bb + byt + 16)  = h1;
            *(uint4*)(Bb + byt + 128) = l0;
            *(uint4*)(Bb + byt + 144) = l1;
        }
        __syncthreads();   // A' + B' visible

        // ---- HMMA: 3 terms x 4 k-steps, warp tile 16x16 ----
        float d[2][4];
#pragma unroll
        for (int n8 = 0; n8 < 2; n8++)
#pragma unroll
            for (int e = 0; e < 4; e++) d[n8][e] = 0.f;

#pragma unroll
        for (int s = 0; s < 3; s++) {
            const uint32_t aOff = (s == 2) ? 128u : 0u;   // UL slice
            const uint32_t bOff = (s == 1) ? 128u : 0u;   // KL slice
#pragma unroll
            for (int ks = 0; ks < 4; ks++) {
                uint32_t a0[4], b0[4];
                LDSM4(a0, aAddr + aOff + ks * 32);
                LDSM4(b0, bAddr + bOff + ks * 32);
                MMA16816(d[0], a0, b0[0], b0[1]);
                MMA16816(d[1], a0, b0[2], b0[3]);
            }
        }

        // ---- scatter fragments into OUT smem (bank-cheap) ----
        {
            int row0 = wr + (lid >> 2);
            int p0   = wc + (lid & 3) * 2;
#pragma unroll
            for (int n8 = 0; n8 < 2; n8++) {
                int p = p0 + n8 * 8;
                if (p < len) {
                    int jp = jperm[off + p];
                    OUT[row0 * OSTR + jp]       = d[n8][0];
                    OUT[(row0 + 8) * OSTR + jp] = d[n8][2];
                }
                if (p + 1 < len) {
                    int jp = jperm[off + p + 1];
                    OUT[row0 * OSTR + jp]       = d[n8][1];
                    OUT[(row0 + 8) * OSTR + jp] = d[n8][3];
                }
            }
        }
        __syncthreads();   // B'/A' reads done before next chunk overwrites
    }

    // ---- coalesced flush: OUT smem -> gmem (ALL 32*128 float4s) ----
    float* outbase = out + ((size_t)bh * SLEN + i0) * SLEN;
    for (int x = tid; x < TI * (SLEN / 4); x += 256) {
        int row = x >> 7;          // 0..31
        int f4  = x & 127;         // float4 index within row
        ((float4*)(outbase + (size_t)row * SLEN))[f4] =
            *(const float4*)(OUT + row * OSTR + f4 * 4);
    }
}

// ---------------- launch ----------------
extern "C" void kernel_launch(void* const* d_in, const int* in_sizes, int n_in,
                              void* d_out, int out_size) {
    const float* q      = (const float*)d_in[0];
    const float* kk     = (const float*)d_in[1];
    const int*   bseq   = (const int*)  d_in[2];
    const float* W1     = (const float*)d_in[3];
    const float* alpha1 = (const float*)d_in[4];
    float* out = (float*)d_out;

    cudaFuncSetAttribute(mb_scores_kernel,
                         cudaFuncAttributeMaxDynamicSharedMemorySize, SMEM_BYTES);

    prep_kernel<<<KSPLIT_BLOCKS + WMIX_BLOCKS, 256>>>(W1, alpha1, kk);

    dim3 g2(SLEN / TI, HNUM, BNUM);   // (16, 8, 8) = 1024 blocks
    mb_scores_kernel<<<g2, 256, SMEM_BYTES>>>(q, bseq, out);
}